// round 7
// baseline (speedup 1.0000x reference)
#include <cuda_runtime.h>
#include <math.h>

#define D_MODEL 1024
#define N_HEADS 16
#define DH      64
#define BATCH   2
#define SEQ     2048
#define BT      (BATCH * SEQ)      // 4096
#define D3      (3 * D_MODEL)      // 3072

// ---------------- scratch (device globals; no allocation allowed) ----------
__device__ float g_qkv[(size_t)3 * BT * D_MODEL];     // [3][B*H][T][DH]
__device__ float g_attn[(size_t)BT * D_MODEL];        // [B,T,D]

// ---------------- helpers ----------------------------------------------------
__device__ __forceinline__ unsigned f2tf32(float f) {
    unsigned r;
    asm("cvt.rna.tf32.f32 %0, %1;" : "=r"(r) : "f"(f));
    return r;
}

__device__ __forceinline__ void mma_tf32(
    float& c0, float& c1, float& c2, float& c3,
    unsigned a0, unsigned a1, unsigned a2, unsigned a3,
    unsigned b0, unsigned b1) {
    asm volatile(
        "mma.sync.aligned.m16n8k8.row.col.f32.tf32.tf32.f32 "
        "{%0,%1,%2,%3}, {%4,%5,%6,%7}, {%8,%9}, {%0,%1,%2,%3};"
        : "+f"(c0), "+f"(c1), "+f"(c2), "+f"(c3)
        : "r"(a0), "r"(a1), "r"(a2), "r"(a3), "r"(b0), "r"(b1));
}

// ---------------- TF32 GEMM: C[M,N] = A[M,K] @ W[N,K]^T ----------------------
// Block tile 128x64 (SMALLER -> 32 acc regs -> 3 CTAs/SM, 24 warps), k-step 32,
// cp.async 2-stage double buffer, tf32 conversion at fragment-load time.
#define KSTEP 32
#define SPAD  36
#define BM    128
#define BN    64
#define STAGE_FLOATS ((BM + BN) * SPAD)                // 6912
#define STAGE_BYTES  (STAGE_FLOATS * 4)
#define GEMM_SMEM_BYTES (2 * STAGE_BYTES)               // 55296

template <int MODE>
__global__ __launch_bounds__(256, 3) void gemm_tf32_kernel(
    const float* __restrict__ A, const float* __restrict__ W,
    float* __restrict__ C, int M, int N, int K) {
    extern __shared__ float smem[];
    unsigned smem_u32;
    asm("{ .reg .u64 t; cvta.to.shared.u64 t, %1; cvt.u32.u64 %0, t; }"
        : "=r"(smem_u32) : "l"(smem));

    const int tid  = threadIdx.x;
    const int lane = tid & 31;
    const int wid  = tid >> 5;
    const int warp_m = wid & 3;        // 0..3 -> 32-row slice
    const int warp_n = wid >> 2;       // 0..1 -> 32-col slice
    const int bm = blockIdx.y * BM;
    const int bn = blockIdx.x * BN;
    const int lr = lane >> 2;
    const int lc = lane & 3;

    // copy mapping: thread covers rows c_row+32*it, 16B at col c_col
    const int c_row = tid >> 3;        // 0..31
    const int c_col = (tid & 7) * 4;   // 0..28
    const float* Abase = A + (size_t)(bm + c_row) * K + c_col;
    const float* Wbase = W + (size_t)(bn + c_row) * K + c_col;

#define COPY_TILE(k0, s) {                                                     \
        unsigned base_ = smem_u32 + (unsigned)((s) * STAGE_BYTES);             \
        _Pragma("unroll")                                                      \
        for (int it = 0; it < 4; it++) {                                       \
            int row_ = c_row + 32 * it;                                        \
            unsigned da_ = base_ + (unsigned)((row_ * SPAD + c_col) * 4);      \
            const float* sa_ = Abase + (size_t)(32 * it) * K + (k0);           \
            asm volatile("cp.async.cg.shared.global [%0], [%1], 16;"           \
                         :: "r"(da_), "l"(sa_));                               \
        }                                                                      \
        _Pragma("unroll")                                                      \
        for (int it = 0; it < 2; it++) {                                       \
            int row_ = c_row + 32 * it;                                        \
            unsigned db_ = base_ +                                             \
                (unsigned)((BM * SPAD + row_ * SPAD + c_col) * 4);             \
            const float* sb_ = Wbase + (size_t)(32 * it) * K + (k0);           \
            asm volatile("cp.async.cg.shared.global [%0], [%1], 16;"           \
                         :: "r"(db_), "l"(sb_));                               \
        }                                                                      \
        asm volatile("cp.async.commit_group;"); }

    float acc[2][4][4];
    #pragma unroll
    for (int i = 0; i < 2; i++)
        #pragma unroll
        for (int j = 0; j < 4; j++)
            #pragma unroll
            for (int c = 0; c < 4; c++) acc[i][j][c] = 0.f;

    COPY_TILE(0, 0);

    const int nk = K / KSTEP;
    for (int i = 0; i < nk; i++) {
        asm volatile("cp.async.wait_group 0;");
        __syncthreads();
        if (i + 1 < nk) COPY_TILE((i + 1) * KSTEP, (i + 1) & 1);

        const float* As_ = smem + (size_t)(i & 1) * STAGE_FLOATS;
        const float* Bs_ = As_ + BM * SPAD;

        #pragma unroll
        for (int kk = 0; kk < KSTEP; kk += 8) {
            unsigned a[2][4];
            #pragma unroll
            for (int ii = 0; ii < 2; ii++) {
                int m = warp_m * 32 + ii * 16;
                a[ii][0] = f2tf32(As_[(m + lr) * SPAD + kk + lc]);
                a[ii][1] = f2tf32(As_[(m + lr + 8) * SPAD + kk + lc]);
                a[ii][2] = f2tf32(As_[(m + lr) * SPAD + kk + lc + 4]);
                a[ii][3] = f2tf32(As_[(m + lr + 8) * SPAD + kk + lc + 4]);
            }
            #pragma unroll
            for (int j = 0; j < 4; j++) {
                int n = warp_n * 32 + j * 8;
                unsigned b0 = f2tf32(Bs_[(n + lr) * SPAD + kk + lc]);
                unsigned b1 = f2tf32(Bs_[(n + lr) * SPAD + kk + lc + 4]);
                #pragma unroll
                for (int ii = 0; ii < 2; ii++)
                    mma_tf32(acc[ii][j][0], acc[ii][j][1], acc[ii][j][2], acc[ii][j][3],
                             a[ii][0], a[ii][1], a[ii][2], a[ii][3], b0, b1);
            }
        }
    }
#undef COPY_TILE

    #pragma unroll
    for (int i = 0; i < 2; i++) {
        #pragma unroll
        for (int j = 0; j < 4; j++) {
            #pragma unroll
            for (int c = 0; c < 4; c++) {
                int m = bm + warp_m * 32 + i * 16 + lr + ((c >= 2) ? 8 : 0);
                int n = bn + warp_n * 32 + j * 8 + 2 * lc + (c & 1);
                if (MODE == 0) {
                    int b = m >> 11;
                    int t = m & (SEQ - 1);
                    int which = n >> 10;
                    int d = n & (D_MODEL - 1);
                    int h = d >> 6;
                    int hd = d & 63;
                    size_t dst = (size_t)which * ((size_t)BT * D_MODEL) +
                                 (((size_t)(b * N_HEADS + h) * SEQ + t) << 6) + hd;
                    C[dst] = acc[i][j][c];
                } else {
                    C[(size_t)m * N + n] = acc[i][j][c];
                }
            }
        }
    }
}

// ---------------- TF32 tensor-core causal flash attention (R3 version) -------
#define QT 128
#define KT 64
#define KS_PAD 68
#define VS_PAD 72

__global__ __launch_bounds__(256) void attn_mma_kernel(
    const float* __restrict__ qkv, float* __restrict__ out) {
    __shared__ __align__(16) unsigned Ks[KT][KS_PAD];
    __shared__ __align__(16) unsigned Vs[KT][VS_PAD];

    const int tid  = threadIdx.x;
    const int lane = tid & 31;
    const int wid  = tid >> 5;
    const int lr = lane >> 2;
    const int lc = lane & 3;

    const int bh = blockIdx.y;
    const int qt = (gridDim.x - 1) - blockIdx.x;   // heavy tiles first
    const int q0 = qt * QT;

    const float* Qp = qkv + ((size_t)bh * SEQ + q0) * DH;
    const float* Kp = qkv + (size_t)BT * D_MODEL + (size_t)bh * SEQ * DH;
    const float* Vp = qkv + (size_t)2 * BT * D_MODEL + (size_t)bh * SEQ * DH;

    unsigned qa[8][4];
    {
        const int r0 = wid * 16 + lr;
        #pragma unroll
        for (int kk = 0; kk < 8; kk++) {
            int c = kk * 8 + lc;
            qa[kk][0] = f2tf32(0.125f * Qp[(size_t)r0 * DH + c]);
            qa[kk][1] = f2tf32(0.125f * Qp[(size_t)(r0 + 8) * DH + c]);
            qa[kk][2] = f2tf32(0.125f * Qp[(size_t)r0 * DH + c + 4]);
            qa[kk][3] = f2tf32(0.125f * Qp[(size_t)(r0 + 8) * DH + c + 4]);
        }
    }

    float o[8][4];
    #pragma unroll
    for (int n = 0; n < 8; n++)
        #pragma unroll
        for (int c = 0; c < 4; c++) o[n][c] = 0.f;
    float m0 = -1e30f, m1 = -1e30f, l0 = 0.f, l1 = 0.f;

    const int nkt = 2 * qt + 2;
    const int row0 = q0 + wid * 16 + lr;
    const int row1 = row0 + 8;

    for (int kt = 0; kt < nkt; kt++) {
        const int k0 = kt * KT;
        __syncthreads();
        #pragma unroll
        for (int it = 0; it < 4; it++) {
            int i = tid + 256 * it;
            int r = i >> 4;
            int c = (i & 15) * 4;
            float4 kv = *(const float4*)&Kp[(size_t)(k0 + r) * DH + c];
            *(uint4*)&Ks[r][c] = make_uint4(f2tf32(kv.x), f2tf32(kv.y),
                                            f2tf32(kv.z), f2tf32(kv.w));
            float4 vv = *(const float4*)&Vp[(size_t)(k0 + r) * DH + c];
            *(uint4*)&Vs[r][c] = make_uint4(f2tf32(vv.x), f2tf32(vv.y),
                                            f2tf32(vv.z), f2tf32(vv.w));
        }
        __syncthreads();

        float s[8][4];
        #pragma unroll
        for (int n = 0; n < 8; n++)
            #pragma unroll
            for (int c = 0; c < 4; c++) s[n][c] = 0.f;

        #pragma unroll
        for (int n = 0; n < 8; n++) {
            #pragma unroll
            for (int kk = 0; kk < 8; kk++) {
                unsigned b0 = Ks[n * 8 + lr][kk * 8 + lc];
                unsigned b1 = Ks[n * 8 + lr][kk * 8 + lc + 4];
                mma_tf32(s[n][0], s[n][1], s[n][2], s[n][3],
                         qa[kk][0], qa[kk][1], qa[kk][2], qa[kk][3], b0, b1);
            }
        }

        if (kt >= 2 * qt) {
            #pragma unroll
            for (int n = 0; n < 8; n++) {
                int col0 = k0 + n * 8 + 2 * lc;
                if (col0 > row0)     s[n][0] = -1e30f;
                if (col0 + 1 > row0) s[n][1] = -1e30f;
                if (col0 > row1)     s[n][2] = -1e30f;
                if (col0 + 1 > row1) s[n][3] = -1e30f;
            }
        }

        float mx0 = -1e30f, mx1 = -1e30f;
        #pragma unroll
        for (int n = 0; n < 8; n++) {
            mx0 = fmaxf(mx0, fmaxf(s[n][0], s[n][1]));
            mx1 = fmaxf(mx1, fmaxf(s[n][2], s[n][3]));
        }
        mx0 = fmaxf(mx0, __shfl_xor_sync(0xffffffffu, mx0, 1));
        mx0 = fmaxf(mx0, __shfl_xor_sync(0xffffffffu, mx0, 2));
        mx1 = fmaxf(mx1, __shfl_xor_sync(0xffffffffu, mx1, 1));
        mx1 = fmaxf(mx1, __shfl_xor_sync(0xffffffffu, mx1, 2));

        float mn0 = fmaxf(m0, mx0), mn1 = fmaxf(m1, mx1);
        float alpha0 = __expf(m0 - mn0), alpha1 = __expf(m1 - mn1);
        m0 = mn0; m1 = mn1;

        float sum0 = 0.f, sum1 = 0.f;
        #pragma unroll
        for (int n = 0; n < 8; n++) {
            s[n][0] = __expf(s[n][0] - mn0);
            s[n][1] = __expf(s[n][1] - mn0);
            s[n][2] = __expf(s[n][2] - mn1);
            s[n][3] = __expf(s[n][3] - mn1);
            sum0 += s[n][0] + s[n][1];
            sum1 += s[n][2] + s[n][3];
        }
        sum0 += __shfl_xor_sync(0xffffffffu, sum0, 1);
        sum0 += __shfl_xor_sync(0xffffffffu, sum0, 2);
        sum1 += __shfl_xor_sync(0xffffffffu, sum1, 1);
        sum1 += __shfl_xor_sync(0xffffffffu, sum1, 2);
        l0 = l0 * alpha0 + sum0;
        l1 = l1 * alpha1 + sum1;

        #pragma unroll
        for (int n = 0; n < 8; n++) {
            o[n][0] *= alpha0; o[n][1] *= alpha0;
            o[n][2] *= alpha1; o[n][3] *= alpha1;
        }

        const int qbase = lane & ~3;
        const int h0 = qbase + (lc >> 1);
        const int h1 = h0 + 2;
        const bool odd = lc & 1;
        #pragma unroll
        for (int n = 0; n < 8; n++) {
            float t0 = __shfl_sync(0xffffffffu, s[n][0], h0);
            float t1 = __shfl_sync(0xffffffffu, s[n][1], h0);
            float u0 = __shfl_sync(0xffffffffu, s[n][0], h1);
            float u1 = __shfl_sync(0xffffffffu, s[n][1], h1);
            float v0 = __shfl_sync(0xffffffffu, s[n][2], h0);
            float v1 = __shfl_sync(0xffffffffu, s[n][3], h0);
            float w0 = __shfl_sync(0xffffffffu, s[n][2], h1);
            float w1 = __shfl_sync(0xffffffffu, s[n][3], h1);
            s[n][0] = __uint_as_float(f2tf32(odd ? t1 : t0));
            s[n][1] = __uint_as_float(f2tf32(odd ? v1 : v0));
            s[n][2] = __uint_as_float(f2tf32(odd ? u1 : u0));
            s[n][3] = __uint_as_float(f2tf32(odd ? w1 : w0));
        }

        #pragma unroll
        for (int d = 0; d < 8; d++) {
            #pragma unroll
            for (int kk = 0; kk < 8; kk++) {
                unsigned b0 = Vs[kk * 8 + lc][d * 8 + lr];
                unsigned b1 = Vs[kk * 8 + lc + 4][d * 8 + lr];
                mma_tf32(o[d][0], o[d][1], o[d][2], o[d][3],
                         __float_as_uint(s[kk][0]), __float_as_uint(s[kk][1]),
                         __float_as_uint(s[kk][2]), __float_as_uint(s[kk][3]),
                         b0, b1);
            }
        }
    }

    const int b = bh >> 4;
    const int h = bh & 15;
    const float inv0 = 1.f / l0;
    const float inv1 = 1.f / l1;
    #pragma unroll
    for (int n = 0; n < 8; n++) {
        int d = h * DH + n * 8 + 2 * lc;
        float2 r0v = make_float2(o[n][0] * inv0, o[n][1] * inv0);
        float2 r1v = make_float2(o[n][2] * inv1, o[n][3] * inv1);
        *(float2*)&out[((size_t)(b * SEQ + row0)) * D_MODEL + d] = r0v;
        *(float2*)&out[((size_t)(b * SEQ + row1)) * D_MODEL + d] = r1v;
    }
}

// ---------------- launch ------------------------------------------------------
extern "C" void kernel_launch(void* const* d_in, const int* in_sizes, int n_in,
                              void* d_out, int out_size) {
    const float* x     = (const float*)d_in[0];
    const float* W_in  = (const float*)d_in[1];
    const float* W_out = (const float*)d_in[2];
    float* out = (float*)d_out;

    float *qkv, *attn;
    cudaGetSymbolAddress((void**)&qkv,  g_qkv);
    cudaGetSymbolAddress((void**)&attn, g_attn);

    cudaFuncSetAttribute(gemm_tf32_kernel<0>,
                         cudaFuncAttributeMaxDynamicSharedMemorySize, GEMM_SMEM_BYTES);
    cudaFuncSetAttribute(gemm_tf32_kernel<1>,
                         cudaFuncAttributeMaxDynamicSharedMemorySize, GEMM_SMEM_BYTES);

    // 1. QKV projection (TF32 mma + cp.async, 128x64 tile)
    {
        dim3 grid(D3 / BN, BT / BM);          // (48, 32)
        gemm_tf32_kernel<0><<<grid, 256, GEMM_SMEM_BYTES>>>(x, W_in, qkv, BT, D3, D_MODEL);
    }

    // 2. causal flash attention (TF32 mma) -> g_attn [B,T,D]
    {
        dim3 grid(SEQ / QT, BATCH * N_HEADS); // (16, 32)
        attn_mma_kernel<<<grid, 256>>>(qkv, attn);
    }

    // 3. output projection (TF32 mma + cp.async, 128x64 tile) -> d_out
    {
        dim3 grid(D_MODEL / BN, BT / BM);     // (16, 32)
        gemm_tf32_kernel<1><<<grid, 256, GEMM_SMEM_BYTES>>>(attn, W_out, out, BT, D_MODEL, D_MODEL);
    }
}

// round 9
// speedup vs baseline: 1.0908x; 1.0908x over previous
#include <cuda_runtime.h>
#include <math.h>

#define D_MODEL 1024
#define N_HEADS 16
#define DH      64
#define BATCH   2
#define SEQ     2048
#define BT      (BATCH * SEQ)      // 4096
#define D3      (3 * D_MODEL)      // 3072

// ---------------- scratch (device globals; no allocation allowed) ----------
__device__ float g_xr[(size_t)BT * D_MODEL];          // x pre-rounded to tf32
__device__ float g_winr[(size_t)D3 * D_MODEL];        // W_in pre-rounded
__device__ float g_woutr[(size_t)D_MODEL * D_MODEL];  // W_out pre-rounded
__device__ float g_qkv[(size_t)3 * BT * D_MODEL];     // [3][B*H][T][DH]
__device__ float g_attn[(size_t)BT * D_MODEL];        // [B,T,D] (tf32-rounded)

// ---------------- helpers ----------------------------------------------------
__device__ __forceinline__ unsigned f2tf32(float f) {
    unsigned r;
    asm("cvt.rna.tf32.f32 %0, %1;" : "=r"(r) : "f"(f));
    return r;
}

__device__ __forceinline__ void mma_tf32(
    float& c0, float& c1, float& c2, float& c3,
    unsigned a0, unsigned a1, unsigned a2, unsigned a3,
    unsigned b0, unsigned b1) {
    asm volatile(
        "mma.sync.aligned.m16n8k8.row.col.f32.tf32.tf32.f32 "
        "{%0,%1,%2,%3}, {%4,%5,%6,%7}, {%8,%9}, {%0,%1,%2,%3};"
        : "+f"(c0), "+f"(c1), "+f"(c2), "+f"(c3)
        : "r"(a0), "r"(a1), "r"(a2), "r"(a3), "r"(b0), "r"(b1));
}

// ldmatrix x4: delivers reg r_s to lane t as 32-bit element (t/4, t%4) of the
// four 8x4 subtiles (validated in R6: bit-identical results).
__device__ __forceinline__ void ldsm_x4(
    unsigned& r0, unsigned& r1, unsigned& r2, unsigned& r3, unsigned addr) {
    asm volatile("ldmatrix.sync.aligned.m8n8.x4.shared.b16 {%0,%1,%2,%3}, [%4];"
                 : "=r"(r0), "=r"(r1), "=r"(r2), "=r"(r3) : "r"(addr));
}

__device__ __forceinline__ unsigned smem_u32_of(const void* p) {
    unsigned r;
    asm("{ .reg .u64 t; cvta.to.shared.u64 t, %1; cvt.u32.u64 %0, t; }"
        : "=r"(r) : "l"(p));
    return r;
}

// ---------------- tf32 pre-rounding kernel ------------------------------------
__global__ __launch_bounds__(256) void round_tf32_kernel(
    const float* __restrict__ in, float* __restrict__ out, int n4) {
    int i = blockIdx.x * 256 + threadIdx.x;
    if (i < n4) {
        float4 v = ((const float4*)in)[i];
        ((uint4*)out)[i] =
            make_uint4(f2tf32(v.x), f2tf32(v.y), f2tf32(v.z), f2tf32(v.w));
    }
}

// ---------------- TF32 GEMM: C[M,N] = A[M,K] @ W[N,K]^T ----------------------
// Inputs PRE-ROUNDED to tf32 in gmem. Block 128x128, k-step 32, cp.async
// 2-stage double buffer, ldmatrix fragment loads. Mainloop = LDSM + HMMA only.
#define KSTEP 32
#define SPAD  36
#define STAGE_FLOATS (2 * 128 * SPAD)                  // A + B per stage
#define STAGE_BYTES  (STAGE_FLOATS * 4)
#define GEMM_SMEM_BYTES (2 * STAGE_BYTES)               // 73728

template <int MODE>
__global__ __launch_bounds__(256, 2) void gemm_tf32_kernel(
    const float* __restrict__ A, const float* __restrict__ W,
    float* __restrict__ C, int M, int N, int K) {
    extern __shared__ float smem[];
    const unsigned smem_u32 = smem_u32_of(smem);

    const int tid  = threadIdx.x;
    const int lane = tid & 31;
    const int wid  = tid >> 5;
    const int warp_m = wid & 3;
    const int warp_n = wid >> 2;
    const int bm = blockIdx.y * 128;
    const int bn = blockIdx.x * 128;
    const int lr = lane >> 2;
    const int lc = lane & 3;

    // copy mapping: thread covers rows c_row+32*it, 16B at col c_col
    const int c_row = tid >> 3;        // 0..31
    const int c_col = (tid & 7) * 4;   // 0..28
    const float* Abase = A + (size_t)(bm + c_row) * K + c_col;
    const float* Wbase = W + (size_t)(bn + c_row) * K + c_col;

    // ldmatrix lane offsets (bytes within a stage) — validated in R6
    const int ls  = lane >> 3;               // subtile 0..3
    const int rin = lane & 7;
    const int fr  = ((ls & 1) << 3) + rin;   // +8 rows for odd subtile
    const int fc  = (ls >> 1) * 4;           // +4 cols for subtiles 2,3
    const unsigned a_off0 = (unsigned)(((warp_m * 32 + fr) * SPAD + fc) * 4);
    const unsigned a_off1 = (unsigned)(((warp_m * 32 + 16 + fr) * SPAD + fc) * 4);
    unsigned b_off[4];
    #pragma unroll
    for (int jj = 0; jj < 4; jj++)
        b_off[jj] = (unsigned)((128 * SPAD + (warp_n * 64 + jj * 16 + fr) * SPAD + fc) * 4);

#define COPY_TILE(k0, s) {                                                     \
        unsigned base_ = smem_u32 + (unsigned)((s) * STAGE_BYTES);             \
        _Pragma("unroll")                                                      \
        for (int it = 0; it < 4; it++) {                                       \
            int row_ = c_row + 32 * it;                                        \
            unsigned da_ = base_ + (unsigned)((row_ * SPAD + c_col) * 4);      \
            const float* sa_ = Abase + (size_t)(32 * it) * K + (k0);           \
            asm volatile("cp.async.cg.shared.global [%0], [%1], 16;"           \
                         :: "r"(da_), "l"(sa_));                               \
            unsigned db_ = base_ +                                             \
                (unsigned)((128 * SPAD + row_ * SPAD + c_col) * 4);            \
            const float* sb_ = Wbase + (size_t)(32 * it) * K + (k0);           \
            asm volatile("cp.async.cg.shared.global [%0], [%1], 16;"           \
                         :: "r"(db_), "l"(sb_));                               \
        }                                                                      \
        asm volatile("cp.async.commit_group;"); }

    float acc[2][8][4];
    #pragma unroll
    for (int i = 0; i < 2; i++)
        #pragma unroll
        for (int j = 0; j < 8; j++)
            #pragma unroll
            for (int c = 0; c < 4; c++) acc[i][j][c] = 0.f;

    COPY_TILE(0, 0);

    const int nk = K / KSTEP;
    for (int i = 0; i < nk; i++) {
        asm volatile("cp.async.wait_group 0;");
        __syncthreads();
        if (i + 1 < nk) COPY_TILE((i + 1) * KSTEP, (i + 1) & 1);

        const unsigned sbase = smem_u32 + (unsigned)((i & 1) * STAGE_BYTES);
        #pragma unroll
        for (int kk = 0; kk < KSTEP; kk += 8) {
            unsigned a[2][4];
            ldsm_x4(a[0][0], a[0][1], a[0][2], a[0][3], sbase + a_off0 + kk * 4);
            ldsm_x4(a[1][0], a[1][1], a[1][2], a[1][3], sbase + a_off1 + kk * 4);
            #pragma unroll
            for (int jj = 0; jj < 4; jj++) {
                unsigned b0a, b0b, b1a, b1b;
                ldsm_x4(b0a, b0b, b1a, b1b, sbase + b_off[jj] + kk * 4);
                int j0 = 2 * jj, j1 = 2 * jj + 1;
                mma_tf32(acc[0][j0][0], acc[0][j0][1], acc[0][j0][2], acc[0][j0][3],
                         a[0][0], a[0][1], a[0][2], a[0][3], b0a, b1a);
                mma_tf32(acc[1][j0][0], acc[1][j0][1], acc[1][j0][2], acc[1][j0][3],
                         a[1][0], a[1][1], a[1][2], a[1][3], b0a, b1a);
                mma_tf32(acc[0][j1][0], acc[0][j1][1], acc[0][j1][2], acc[0][j1][3],
                         a[0][0], a[0][1], a[0][2], a[0][3], b0b, b1b);
                mma_tf32(acc[1][j1][0], acc[1][j1][1], acc[1][j1][2], acc[1][j1][3],
                         a[1][0], a[1][1], a[1][2], a[1][3], b0b, b1b);
            }
        }
    }
#undef COPY_TILE

    #pragma unroll
    for (int i = 0; i < 2; i++) {
        #pragma unroll
        for (int j = 0; j < 8; j++) {
            #pragma unroll
            for (int c = 0; c < 4; c++) {
                int m = bm + warp_m * 32 + i * 16 + lr + ((c >= 2) ? 8 : 0);
                int n = bn + warp_n * 64 + j * 8 + 2 * lc + (c & 1);
                if (MODE == 0) {
                    int b = m >> 11;
                    int t = m & (SEQ - 1);
                    int which = n >> 10;
                    int d = n & (D_MODEL - 1);
                    int h = d >> 6;
                    int hd = d & 63;
                    size_t dst = (size_t)which * ((size_t)BT * D_MODEL) +
                                 (((size_t)(b * N_HEADS + h) * SEQ + t) << 6) + hd;
                    C[dst] = acc[i][j][c];
                } else {
                    C[(size_t)m * N + n] = acc[i][j][c];
                }
            }
        }
    }
}

// ---------------- TF32 tensor-core causal flash attention (R3, unchanged) ----
#define QT 128
#define KT 64
#define KS_PAD 68
#define VS_PAD 72

__global__ __launch_bounds__(256) void attn_mma_kernel(
    const float* __restrict__ qkv, float* __restrict__ out) {
    __shared__ __align__(16) unsigned Ks[KT][KS_PAD];
    __shared__ __align__(16) unsigned Vs[KT][VS_PAD];

    const int tid  = threadIdx.x;
    const int lane = tid & 31;
    const int wid  = tid >> 5;
    const int lr = lane >> 2;
    const int lc = lane & 3;

    const int bh = blockIdx.y;
    const int qt = (gridDim.x - 1) - blockIdx.x;   // heavy tiles first
    const int q0 = qt * QT;

    const float* Qp = qkv + ((size_t)bh * SEQ + q0) * DH;
    const float* Kp = qkv + (size_t)BT * D_MODEL + (size_t)bh * SEQ * DH;
    const float* Vp = qkv + (size_t)2 * BT * D_MODEL + (size_t)bh * SEQ * DH;

    unsigned qa[8][4];
    {
        const int r0 = wid * 16 + lr;
        #pragma unroll
        for (int kk = 0; kk < 8; kk++) {
            int c = kk * 8 + lc;
            qa[kk][0] = f2tf32(0.125f * Qp[(size_t)r0 * DH + c]);
            qa[kk][1] = f2tf32(0.125f * Qp[(size_t)(r0 + 8) * DH + c]);
            qa[kk][2] = f2tf32(0.125f * Qp[(size_t)r0 * DH + c + 4]);
            qa[kk][3] = f2tf32(0.125f * Qp[(size_t)(r0 + 8) * DH + c + 4]);
        }
    }

    float o[8][4];
    #pragma unroll
    for (int n = 0; n < 8; n++)
        #pragma unroll
        for (int c = 0; c < 4; c++) o[n][c] = 0.f;
    float m0 = -1e30f, m1 = -1e30f, l0 = 0.f, l1 = 0.f;

    const int nkt = 2 * qt + 2;
    const int row0 = q0 + wid * 16 + lr;
    const int row1 = row0 + 8;

    for (int kt = 0; kt < nkt; kt++) {
        const int k0 = kt * KT;
        __syncthreads();
        #pragma unroll
        for (int it = 0; it < 4; it++) {
            int i = tid + 256 * it;
            int r = i >> 4;
            int c = (i & 15) * 4;
            float4 kv = *(const float4*)&Kp[(size_t)(k0 + r) * DH + c];
            *(uint4*)&Ks[r][c] = make_uint4(f2tf32(kv.x), f2tf32(kv.y),
                                            f2tf32(kv.z), f2tf32(kv.w));
            float4 vv = *(const float4*)&Vp[(size_t)(k0 + r) * DH + c];
            *(uint4*)&Vs[r][c] = make_uint4(f2tf32(vv.x), f2tf32(vv.y),
                                            f2tf32(vv.z), f2tf32(vv.w));
        }
        __syncthreads();

        float s[8][4];
        #pragma unroll
        for (int n = 0; n < 8; n++)
            #pragma unroll
            for (int c = 0; c < 4; c++) s[n][c] = 0.f;

        #pragma unroll
        for (int n = 0; n < 8; n++) {
            #pragma unroll
            for (int kk = 0; kk < 8; kk++) {
                unsigned b0 = Ks[n * 8 + lr][kk * 8 + lc];
                unsigned b1 = Ks[n * 8 + lr][kk * 8 + lc + 4];
                mma_tf32(s[n][0], s[n][1], s[n][2], s[n][3],
                         qa[kk][0], qa[kk][1], qa[kk][2], qa[kk][3], b0, b1);
            }
        }

        if (kt >= 2 * qt) {
            #pragma unroll
            for (int n = 0; n < 8; n++) {
                int col0 = k0 + n * 8 + 2 * lc;
                if (col0 > row0)     s[n][0] = -1e30f;
                if (col0 + 1 > row0) s[n][1] = -1e30f;
                if (col0 > row1)     s[n][2] = -1e30f;
                if (col0 + 1 > row1) s[n][3] = -1e30f;
            }
        }

        float mx0 = -1e30f, mx1 = -1e30f;
        #pragma unroll
        for (int n = 0; n < 8; n++) {
            mx0 = fmaxf(mx0, fmaxf(s[n][0], s[n][1]));
            mx1 = fmaxf(mx1, fmaxf(s[n][2], s[n][3]));
        }
        mx0 = fmaxf(mx0, __shfl_xor_sync(0xffffffffu, mx0, 1));
        mx0 = fmaxf(mx0, __shfl_xor_sync(0xffffffffu, mx0, 2));
        mx1 = fmaxf(mx1, __shfl_xor_sync(0xffffffffu, mx1, 1));
        mx1 = fmaxf(mx1, __shfl_xor_sync(0xffffffffu, mx1, 2));

        float mn0 = fmaxf(m0, mx0), mn1 = fmaxf(m1, mx1);
        float alpha0 = __expf(m0 - mn0), alpha1 = __expf(m1 - mn1);
        m0 = mn0; m1 = mn1;

        float sum0 = 0.f, sum1 = 0.f;
        #pragma unroll
        for (int n = 0; n < 8; n++) {
            s[n][0] = __expf(s[n][0] - mn0);
            s[n][1] = __expf(s[n][1] - mn0);
            s[n][2] = __expf(s[n][2] - mn1);
            s[n][3] = __expf(s[n][3] - mn1);
            sum0 += s[n][0] + s[n][1];
            sum1 += s[n][2] + s[n][3];
        }
        sum0 += __shfl_xor_sync(0xffffffffu, sum0, 1);
        sum0 += __shfl_xor_sync(0xffffffffu, sum0, 2);
        sum1 += __shfl_xor_sync(0xffffffffu, sum1, 1);
        sum1 += __shfl_xor_sync(0xffffffffu, sum1, 2);
        l0 = l0 * alpha0 + sum0;
        l1 = l1 * alpha1 + sum1;

        #pragma unroll
        for (int n = 0; n < 8; n++) {
            o[n][0] *= alpha0; o[n][1] *= alpha0;
            o[n][2] *= alpha1; o[n][3] *= alpha1;
        }

        const int qbase = lane & ~3;
        const int h0 = qbase + (lc >> 1);
        const int h1 = h0 + 2;
        const bool odd = lc & 1;
        #pragma unroll
        for (int n = 0; n < 8; n++) {
            float t0 = __shfl_sync(0xffffffffu, s[n][0], h0);
            float t1 = __shfl_sync(0xffffffffu, s[n][1], h0);
            float u0 = __shfl_sync(0xffffffffu, s[n][0], h1);
            float u1 = __shfl_sync(0xffffffffu, s[n][1], h1);
            float v0 = __shfl_sync(0xffffffffu, s[n][2], h0);
            float v1 = __shfl_sync(0xffffffffu, s[n][3], h0);
            float w0 = __shfl_sync(0xffffffffu, s[n][2], h1);
            float w1 = __shfl_sync(0xffffffffu, s[n][3], h1);
            s[n][0] = __uint_as_float(f2tf32(odd ? t1 : t0));
            s[n][1] = __uint_as_float(f2tf32(odd ? v1 : v0));
            s[n][2] = __uint_as_float(f2tf32(odd ? u1 : u0));
            s[n][3] = __uint_as_float(f2tf32(odd ? w1 : w0));
        }

        #pragma unroll
        for (int d = 0; d < 8; d++) {
            #pragma unroll
            for (int kk = 0; kk < 8; kk++) {
                unsigned b0 = Vs[kk * 8 + lc][d * 8 + lr];
                unsigned b1 = Vs[kk * 8 + lc + 4][d * 8 + lr];
                mma_tf32(o[d][0], o[d][1], o[d][2], o[d][3],
                         __float_as_uint(s[kk][0]), __float_as_uint(s[kk][1]),
                         __float_as_uint(s[kk][2]), __float_as_uint(s[kk][3]),
                         b0, b1);
            }
        }
    }

    const int b = bh >> 4;
    const int h = bh & 15;
    const float inv0 = 1.f / l0;
    const float inv1 = 1.f / l1;
    #pragma unroll
    for (int n = 0; n < 8; n++) {
        int d = h * DH + n * 8 + 2 * lc;
        // emit tf32-rounded values so the out-proj GEMM consumes them raw
        float2 r0v = make_float2(__uint_as_float(f2tf32(o[n][0] * inv0)),
                                 __uint_as_float(f2tf32(o[n][1] * inv0)));
        float2 r1v = make_float2(__uint_as_float(f2tf32(o[n][2] * inv1)),
                                 __uint_as_float(f2tf32(o[n][3] * inv1)));
        *(float2*)&out[((size_t)(b * SEQ + row0)) * D_MODEL + d] = r0v;
        *(float2*)&out[((size_t)(b * SEQ + row1)) * D_MODEL + d] = r1v;
    }
}

// ---------------- launch ------------------------------------------------------
extern "C" void kernel_launch(void* const* d_in, const int* in_sizes, int n_in,
                              void* d_out, int out_size) {
    const float* x     = (const float*)d_in[0];
    const float* W_in  = (const float*)d_in[1];
    const float* W_out = (const float*)d_in[2];
    float* out = (float*)d_out;

    float *xr, *winr, *woutr, *qkv, *attn;
    cudaGetSymbolAddress((void**)&xr,    g_xr);
    cudaGetSymbolAddress((void**)&winr,  g_winr);
    cudaGetSymbolAddress((void**)&woutr, g_woutr);
    cudaGetSymbolAddress((void**)&qkv,   g_qkv);
    cudaGetSymbolAddress((void**)&attn,  g_attn);

    cudaFuncSetAttribute(gemm_tf32_kernel<0>,
                         cudaFuncAttributeMaxDynamicSharedMemorySize, GEMM_SMEM_BYTES);
    cudaFuncSetAttribute(gemm_tf32_kernel<1>,
                         cudaFuncAttributeMaxDynamicSharedMemorySize, GEMM_SMEM_BYTES);

    // 0. pre-round inputs to tf32 (rna) so the GEMM mainloop has no cvt at all
    round_tf32_kernel<<<(BT * D_MODEL / 4 + 255) / 256, 256>>>(x, xr, BT * D_MODEL / 4);
    round_tf32_kernel<<<(D3 * D_MODEL / 4 + 255) / 256, 256>>>(W_in, winr, D3 * D_MODEL / 4);
    round_tf32_kernel<<<(D_MODEL * D_MODEL / 4 + 255) / 256, 256>>>(W_out, woutr,
                                                                    D_MODEL * D_MODEL / 4);

    // 1. QKV projection (TF32 mma + cp.async + ldmatrix, cvt-free mainloop)
    {
        dim3 grid(D3 / 128, BT / 128);        // (24, 32)
        gemm_tf32_kernel<0><<<grid, 256, GEMM_SMEM_BYTES>>>(xr, winr, qkv, BT, D3, D_MODEL);
    }

    // 2. causal flash attention (TF32 mma) -> g_attn [B,T,D]
    {
        dim3 grid(SEQ / QT, BATCH * N_HEADS); // (16, 32)
        attn_mma_kernel<<<grid, 256>>>(qkv, attn);
    }

    // 3. output projection -> d_out
    {
        dim3 grid(D_MODEL / 128, BT / 128);   // (8, 32)
        gemm_tf32_kernel<1><<<grid, 256, GEMM_SMEM_BYTES>>>(attn, woutr, out, BT, D_MODEL, D_MODEL);
    }
}

// round 10
// speedup vs baseline: 1.1041x; 1.0122x over previous
#include <cuda_runtime.h>
#include <math.h>

#define D_MODEL 1024
#define N_HEADS 16
#define DH      64
#define BATCH   2
#define SEQ     2048
#define BT      (BATCH * SEQ)      // 4096
#define D3      (3 * D_MODEL)      // 3072

// ---------------- scratch (device globals; no allocation allowed) ----------
__device__ float g_xr[(size_t)BT * D_MODEL];          // x pre-rounded to tf32
__device__ float g_winr[(size_t)D3 * D_MODEL];        // W_in pre-rounded
__device__ float g_woutr[(size_t)D_MODEL * D_MODEL];  // W_out pre-rounded
__device__ float g_qkv[(size_t)3 * BT * D_MODEL];     // [3][B*H][T][DH] tf32 bits (q pre-scaled)
__device__ float g_attn[(size_t)BT * D_MODEL];        // [B,T,D] tf32-rounded

// ---------------- helpers ----------------------------------------------------
__device__ __forceinline__ unsigned f2tf32(float f) {
    unsigned r;
    asm("cvt.rna.tf32.f32 %0, %1;" : "=r"(r) : "f"(f));
    return r;
}

__device__ __forceinline__ void mma_tf32(
    float& c0, float& c1, float& c2, float& c3,
    unsigned a0, unsigned a1, unsigned a2, unsigned a3,
    unsigned b0, unsigned b1) {
    asm volatile(
        "mma.sync.aligned.m16n8k8.row.col.f32.tf32.tf32.f32 "
        "{%0,%1,%2,%3}, {%4,%5,%6,%7}, {%8,%9}, {%0,%1,%2,%3};"
        : "+f"(c0), "+f"(c1), "+f"(c2), "+f"(c3)
        : "r"(a0), "r"(a1), "r"(a2), "r"(a3), "r"(b0), "r"(b1));
}

__device__ __forceinline__ void ldsm_x4(
    unsigned& r0, unsigned& r1, unsigned& r2, unsigned& r3, unsigned addr) {
    asm volatile("ldmatrix.sync.aligned.m8n8.x4.shared.b16 {%0,%1,%2,%3}, [%4];"
                 : "=r"(r0), "=r"(r1), "=r"(r2), "=r"(r3) : "r"(addr));
}

__device__ __forceinline__ unsigned smem_u32_of(const void* p) {
    unsigned r;
    asm("{ .reg .u64 t; cvta.to.shared.u64 t, %1; cvt.u32.u64 %0, t; }"
        : "=r"(r) : "l"(p));
    return r;
}

// ---------------- tf32 pre-rounding kernel ------------------------------------
__global__ __launch_bounds__(256) void round_tf32_kernel(
    const float* __restrict__ in, float* __restrict__ out, int n4) {
    int i = blockIdx.x * 256 + threadIdx.x;
    if (i < n4) {
        float4 v = ((const float4*)in)[i];
        ((uint4*)out)[i] =
            make_uint4(f2tf32(v.x), f2tf32(v.y), f2tf32(v.z), f2tf32(v.w));
    }
}

// ---------------- TF32 GEMM: C[M,N] = A[M,K] @ W[N,K]^T ----------------------
// Inputs pre-rounded tf32. Mainloop = LDSM + HMMA only (R9, best measured).
// MODE 0 epilogue: rounds output to tf32 and pre-scales q by 1/8 (feeds attn).
#define KSTEP 32
#define SPAD  36
#define STAGE_FLOATS (2 * 128 * SPAD)
#define STAGE_BYTES  (STAGE_FLOATS * 4)
#define GEMM_SMEM_BYTES (2 * STAGE_BYTES)               // 73728

template <int MODE>
__global__ __launch_bounds__(256, 2) void gemm_tf32_kernel(
    const float* __restrict__ A, const float* __restrict__ W,
    float* __restrict__ C, int M, int N, int K) {
    extern __shared__ float smem[];
    const unsigned smem_u32 = smem_u32_of(smem);

    const int tid  = threadIdx.x;
    const int lane = tid & 31;
    const int wid  = tid >> 5;
    const int warp_m = wid & 3;
    const int warp_n = wid >> 2;
    const int bm = blockIdx.y * 128;
    const int bn = blockIdx.x * 128;
    const int lr = lane >> 2;
    const int lc = lane & 3;

    const int c_row = tid >> 3;
    const int c_col = (tid & 7) * 4;
    const float* Abase = A + (size_t)(bm + c_row) * K + c_col;
    const float* Wbase = W + (size_t)(bn + c_row) * K + c_col;

    const int ls  = lane >> 3;
    const int rin = lane & 7;
    const int fr  = ((ls & 1) << 3) + rin;
    const int fc  = (ls >> 1) * 4;
    const unsigned a_off0 = (unsigned)(((warp_m * 32 + fr) * SPAD + fc) * 4);
    const unsigned a_off1 = (unsigned)(((warp_m * 32 + 16 + fr) * SPAD + fc) * 4);
    unsigned b_off[4];
    #pragma unroll
    for (int jj = 0; jj < 4; jj++)
        b_off[jj] = (unsigned)((128 * SPAD + (warp_n * 64 + jj * 16 + fr) * SPAD + fc) * 4);

#define COPY_TILE(k0, s) {                                                     \
        unsigned base_ = smem_u32 + (unsigned)((s) * STAGE_BYTES);             \
        _Pragma("unroll")                                                      \
        for (int it = 0; it < 4; it++) {                                       \
            int row_ = c_row + 32 * it;                                        \
            unsigned da_ = base_ + (unsigned)((row_ * SPAD + c_col) * 4);      \
            const float* sa_ = Abase + (size_t)(32 * it) * K + (k0);           \
            asm volatile("cp.async.cg.shared.global [%0], [%1], 16;"           \
                         :: "r"(da_), "l"(sa_));                               \
            unsigned db_ = base_ +                                             \
                (unsigned)((128 * SPAD + row_ * SPAD + c_col) * 4);            \
            const float* sb_ = Wbase + (size_t)(32 * it) * K + (k0);           \
            asm volatile("cp.async.cg.shared.global [%0], [%1], 16;"           \
                         :: "r"(db_), "l"(sb_));                               \
        }                                                                      \
        asm volatile("cp.async.commit_group;"); }

    float acc[2][8][4];
    #pragma unroll
    for (int i = 0; i < 2; i++)
        #pragma unroll
        for (int j = 0; j < 8; j++)
            #pragma unroll
            for (int c = 0; c < 4; c++) acc[i][j][c] = 0.f;

    COPY_TILE(0, 0);

    const int nk = K / KSTEP;
    for (int i = 0; i < nk; i++) {
        asm volatile("cp.async.wait_group 0;");
        __syncthreads();
        if (i + 1 < nk) COPY_TILE((i + 1) * KSTEP, (i + 1) & 1);

        const unsigned sbase = smem_u32 + (unsigned)((i & 1) * STAGE_BYTES);
        #pragma unroll
        for (int kk = 0; kk < KSTEP; kk += 8) {
            unsigned a[2][4];
            ldsm_x4(a[0][0], a[0][1], a[0][2], a[0][3], sbase + a_off0 + kk * 4);
            ldsm_x4(a[1][0], a[1][1], a[1][2], a[1][3], sbase + a_off1 + kk * 4);
            #pragma unroll
            for (int jj = 0; jj < 4; jj++) {
                unsigned b0a, b0b, b1a, b1b;
                ldsm_x4(b0a, b0b, b1a, b1b, sbase + b_off[jj] + kk * 4);
                int j0 = 2 * jj, j1 = 2 * jj + 1;
                mma_tf32(acc[0][j0][0], acc[0][j0][1], acc[0][j0][2], acc[0][j0][3],
                         a[0][0], a[0][1], a[0][2], a[0][3], b0a, b1a);
                mma_tf32(acc[1][j0][0], acc[1][j0][1], acc[1][j0][2], acc[1][j0][3],
                         a[1][0], a[1][1], a[1][2], a[1][3], b0a, b1a);
                mma_tf32(acc[0][j1][0], acc[0][j1][1], acc[0][j1][2], acc[0][j1][3],
                         a[0][0], a[0][1], a[0][2], a[0][3], b0b, b1b);
                mma_tf32(acc[1][j1][0], acc[1][j1][1], acc[1][j1][2], acc[1][j1][3],
                         a[1][0], a[1][1], a[1][2], a[1][3], b0b, b1b);
            }
        }
    }
#undef COPY_TILE

    #pragma unroll
    for (int i = 0; i < 2; i++) {
        #pragma unroll
        for (int j = 0; j < 8; j++) {
            #pragma unroll
            for (int c = 0; c < 4; c++) {
                int m = bm + warp_m * 32 + i * 16 + lr + ((c >= 2) ? 8 : 0);
                int n = bn + warp_n * 64 + j * 8 + 2 * lc + (c & 1);
                if (MODE == 0) {
                    int b = m >> 11;
                    int t = m & (SEQ - 1);
                    int which = n >> 10;
                    int d = n & (D_MODEL - 1);
                    int h = d >> 6;
                    int hd = d & 63;
                    size_t dst = (size_t)which * ((size_t)BT * D_MODEL) +
                                 (((size_t)(b * N_HEADS + h) * SEQ + t) << 6) + hd;
                    // round to tf32 here; q additionally pre-scaled by 1/8
                    float v = acc[i][j][c];
                    if (which == 0) v *= 0.125f;
                    C[dst] = __uint_as_float(f2tf32(v));
                } else {
                    C[(size_t)m * N + n] = acc[i][j][c];
                }
            }
        }
    }
}

// ---------------- TF32 tensor-core causal flash attention --------------------
// qkv already tf32 bits (q pre-scaled by 1/8). cp.async double-buffered K/V,
// ldmatrix K fragments, cvt-free mainloop.
#define QT 128
#define KT 64
#define KS_PAD 68
#define VS_PAD 72
#define ATT_STAGE_FLOATS (KT * KS_PAD + KT * VS_PAD)   // 8960
#define ATT_STAGE_BYTES  (ATT_STAGE_FLOATS * 4)        // 35840
#define ATT_SMEM_BYTES   (2 * ATT_STAGE_BYTES)          // 71680

__global__ __launch_bounds__(256) void attn_mma_kernel(
    const float* __restrict__ qkv, float* __restrict__ out) {
    extern __shared__ float asmem[];
    const unsigned sm0 = smem_u32_of(asmem);

    const int tid  = threadIdx.x;
    const int lane = tid & 31;
    const int wid  = tid >> 5;
    const int lr = lane >> 2;
    const int lc = lane & 3;

    const int bh = blockIdx.y;
    const int qt = (gridDim.x - 1) - blockIdx.x;   // heavy tiles first
    const int q0 = qt * QT;

    const float* Qp = qkv + ((size_t)bh * SEQ + q0) * DH;
    const float* Kp = qkv + (size_t)BT * D_MODEL + (size_t)bh * SEQ * DH;
    const float* Vp = qkv + (size_t)2 * BT * D_MODEL + (size_t)bh * SEQ * DH;

    // copy mapping: 8 x 16B chunks/thread per tile (4 K + 4 V)
    const int cp_r = tid >> 2;                     // 0..63  (row, step 16 via it? no:)
    // use R3 mapping: i = tid + 256*it; r = i>>4 (0..63), c=(i&15)*4
    // ldmatrix lane offsets into K region of a stage (bytes)
    const int ls  = lane >> 3;
    const int rin = lane & 7;
    const int fr  = ((ls & 1) << 3) + rin;
    const int fc  = (ls >> 1) * 4;
    unsigned k_off[4];
    #pragma unroll
    for (int jj = 0; jj < 4; jj++)
        k_off[jj] = (unsigned)(((jj * 16 + fr) * KS_PAD + fc) * 4);
    (void)cp_r;

#define ATT_COPY(k0, s) {                                                      \
        unsigned base_ = sm0 + (unsigned)((s) * ATT_STAGE_BYTES);              \
        _Pragma("unroll")                                                      \
        for (int it = 0; it < 4; it++) {                                       \
            int i_ = tid + 256 * it;                                           \
            int r_ = i_ >> 4;                                                  \
            int c_ = (i_ & 15) * 4;                                            \
            unsigned kd_ = base_ + (unsigned)((r_ * KS_PAD + c_) * 4);         \
            asm volatile("cp.async.cg.shared.global [%0], [%1], 16;"           \
                :: "r"(kd_), "l"(Kp + (size_t)((k0) + r_) * DH + c_));         \
            unsigned vd_ = base_ +                                             \
                (unsigned)((KT * KS_PAD + r_ * VS_PAD + c_) * 4);              \
            asm volatile("cp.async.cg.shared.global [%0], [%1], 16;"           \
                :: "r"(vd_), "l"(Vp + (size_t)((k0) + r_) * DH + c_));         \
        }                                                                      \
        asm volatile("cp.async.commit_group;"); }

    // Q fragments: raw bit loads (already tf32, already scaled by 1/8)
    unsigned qa[8][4];
    {
        const int r0 = wid * 16 + lr;
        #pragma unroll
        for (int kk = 0; kk < 8; kk++) {
            int c = kk * 8 + lc;
            qa[kk][0] = __float_as_uint(Qp[(size_t)r0 * DH + c]);
            qa[kk][1] = __float_as_uint(Qp[(size_t)(r0 + 8) * DH + c]);
            qa[kk][2] = __float_as_uint(Qp[(size_t)r0 * DH + c + 4]);
            qa[kk][3] = __float_as_uint(Qp[(size_t)(r0 + 8) * DH + c + 4]);
        }
    }

    float o[8][4];
    #pragma unroll
    for (int n = 0; n < 8; n++)
        #pragma unroll
        for (int c = 0; c < 4; c++) o[n][c] = 0.f;
    float m0 = -1e30f, m1 = -1e30f, l0 = 0.f, l1 = 0.f;

    const int nkt = 2 * qt + 2;
    const int row0 = q0 + wid * 16 + lr;
    const int row1 = row0 + 8;

    ATT_COPY(0, 0);

    for (int kt = 0; kt < nkt; kt++) {
        const int k0 = kt * KT;
        const int s = kt & 1;
        asm volatile("cp.async.wait_group 0;");
        __syncthreads();
        if (kt + 1 < nkt) ATT_COPY((kt + 1) * KT, s ^ 1);

        const unsigned ksbase = sm0 + (unsigned)(s * ATT_STAGE_BYTES);
        const unsigned* Vs_ = (const unsigned*)asmem + (size_t)s * ATT_STAGE_FLOATS
                              + KT * KS_PAD;

        // ---- S = (Q/8) @ K^T via ldmatrix ----
        float sv[8][4];
        #pragma unroll
        for (int n = 0; n < 8; n++)
            #pragma unroll
            for (int c = 0; c < 4; c++) sv[n][c] = 0.f;

        #pragma unroll
        for (int kk = 0; kk < 8; kk++) {
            #pragma unroll
            for (int jj = 0; jj < 4; jj++) {
                unsigned b0a, b0b, b1a, b1b;
                ldsm_x4(b0a, b0b, b1a, b1b, ksbase + k_off[jj] + kk * 32);
                int n0 = 2 * jj, n1 = 2 * jj + 1;
                mma_tf32(sv[n0][0], sv[n0][1], sv[n0][2], sv[n0][3],
                         qa[kk][0], qa[kk][1], qa[kk][2], qa[kk][3], b0a, b1a);
                mma_tf32(sv[n1][0], sv[n1][1], sv[n1][2], sv[n1][3],
                         qa[kk][0], qa[kk][1], qa[kk][2], qa[kk][3], b0b, b1b);
            }
        }

        if (kt >= 2 * qt) {
            #pragma unroll
            for (int n = 0; n < 8; n++) {
                int col0 = k0 + n * 8 + 2 * lc;
                if (col0 > row0)     sv[n][0] = -1e30f;
                if (col0 + 1 > row0) sv[n][1] = -1e30f;
                if (col0 > row1)     sv[n][2] = -1e30f;
                if (col0 + 1 > row1) sv[n][3] = -1e30f;
            }
        }

        float mx0 = -1e30f, mx1 = -1e30f;
        #pragma unroll
        for (int n = 0; n < 8; n++) {
            mx0 = fmaxf(mx0, fmaxf(sv[n][0], sv[n][1]));
            mx1 = fmaxf(mx1, fmaxf(sv[n][2], sv[n][3]));
        }
        mx0 = fmaxf(mx0, __shfl_xor_sync(0xffffffffu, mx0, 1));
        mx0 = fmaxf(mx0, __shfl_xor_sync(0xffffffffu, mx0, 2));
        mx1 = fmaxf(mx1, __shfl_xor_sync(0xffffffffu, mx1, 1));
        mx1 = fmaxf(mx1, __shfl_xor_sync(0xffffffffu, mx1, 2));

        float mn0 = fmaxf(m0, mx0), mn1 = fmaxf(m1, mx1);
        float alpha0 = __expf(m0 - mn0), alpha1 = __expf(m1 - mn1);
        m0 = mn0; m1 = mn1;

        float sum0 = 0.f, sum1 = 0.f;
        #pragma unroll
        for (int n = 0; n < 8; n++) {
            sv[n][0] = __expf(sv[n][0] - mn0);
            sv[n][1] = __expf(sv[n][1] - mn0);
            sv[n][2] = __expf(sv[n][2] - mn1);
            sv[n][3] = __expf(sv[n][3] - mn1);
            sum0 += sv[n][0] + sv[n][1];
            sum1 += sv[n][2] + sv[n][3];
        }
        sum0 += __shfl_xor_sync(0xffffffffu, sum0, 1);
        sum0 += __shfl_xor_sync(0xffffffffu, sum0, 2);
        sum1 += __shfl_xor_sync(0xffffffffu, sum1, 1);
        sum1 += __shfl_xor_sync(0xffffffffu, sum1, 2);
        l0 = l0 * alpha0 + sum0;
        l1 = l1 * alpha1 + sum1;

        #pragma unroll
        for (int n = 0; n < 8; n++) {
            o[n][0] *= alpha0; o[n][1] *= alpha0;
            o[n][2] *= alpha1; o[n][3] *= alpha1;
        }

        // quad-shuffle transpose P -> A-operand layout
        const int qbase = lane & ~3;
        const int h0 = qbase + (lc >> 1);
        const int h1 = h0 + 2;
        const bool odd = lc & 1;
        #pragma unroll
        for (int n = 0; n < 8; n++) {
            float t0 = __shfl_sync(0xffffffffu, sv[n][0], h0);
            float t1 = __shfl_sync(0xffffffffu, sv[n][1], h0);
            float u0 = __shfl_sync(0xffffffffu, sv[n][0], h1);
            float u1 = __shfl_sync(0xffffffffu, sv[n][1], h1);
            float v0 = __shfl_sync(0xffffffffu, sv[n][2], h0);
            float v1 = __shfl_sync(0xffffffffu, sv[n][3], h0);
            float w0 = __shfl_sync(0xffffffffu, sv[n][2], h1);
            float w1 = __shfl_sync(0xffffffffu, sv[n][3], h1);
            sv[n][0] = __uint_as_float(f2tf32(odd ? t1 : t0));
            sv[n][1] = __uint_as_float(f2tf32(odd ? v1 : v0));
            sv[n][2] = __uint_as_float(f2tf32(odd ? u1 : u0));
            sv[n][3] = __uint_as_float(f2tf32(odd ? w1 : w0));
        }

        // ---- O += P @ V ----
        #pragma unroll
        for (int d = 0; d < 8; d++) {
            #pragma unroll
            for (int kk = 0; kk < 8; kk++) {
                unsigned b0 = Vs_[(kk * 8 + lc) * VS_PAD + d * 8 + lr];
                unsigned b1 = Vs_[(kk * 8 + lc + 4) * VS_PAD + d * 8 + lr];
                mma_tf32(o[d][0], o[d][1], o[d][2], o[d][3],
                         __float_as_uint(sv[kk][0]), __float_as_uint(sv[kk][1]),
                         __float_as_uint(sv[kk][2]), __float_as_uint(sv[kk][3]),
                         b0, b1);
            }
        }
    }
#undef ATT_COPY

    const int b = bh >> 4;
    const int h = bh & 15;
    const float inv0 = 1.f / l0;
    const float inv1 = 1.f / l1;
    #pragma unroll
    for (int n = 0; n < 8; n++) {
        int d = h * DH + n * 8 + 2 * lc;
        float2 r0v = make_float2(__uint_as_float(f2tf32(o[n][0] * inv0)),
                                 __uint_as_float(f2tf32(o[n][1] * inv0)));
        float2 r1v = make_float2(__uint_as_float(f2tf32(o[n][2] * inv1)),
                                 __uint_as_float(f2tf32(o[n][3] * inv1)));
        *(float2*)&out[((size_t)(b * SEQ + row0)) * D_MODEL + d] = r0v;
        *(float2*)&out[((size_t)(b * SEQ + row1)) * D_MODEL + d] = r1v;
    }
}

// ---------------- launch ------------------------------------------------------
extern "C" void kernel_launch(void* const* d_in, const int* in_sizes, int n_in,
                              void* d_out, int out_size) {
    const float* x     = (const float*)d_in[0];
    const float* W_in  = (const float*)d_in[1];
    const float* W_out = (const float*)d_in[2];
    float* out = (float*)d_out;

    float *xr, *winr, *woutr, *qkv, *attn;
    cudaGetSymbolAddress((void**)&xr,    g_xr);
    cudaGetSymbolAddress((void**)&winr,  g_winr);
    cudaGetSymbolAddress((void**)&woutr, g_woutr);
    cudaGetSymbolAddress((void**)&qkv,   g_qkv);
    cudaGetSymbolAddress((void**)&attn,  g_attn);

    cudaFuncSetAttribute(gemm_tf32_kernel<0>,
                         cudaFuncAttributeMaxDynamicSharedMemorySize, GEMM_SMEM_BYTES);
    cudaFuncSetAttribute(gemm_tf32_kernel<1>,
                         cudaFuncAttributeMaxDynamicSharedMemorySize, GEMM_SMEM_BYTES);
    cudaFuncSetAttribute(attn_mma_kernel,
                         cudaFuncAttributeMaxDynamicSharedMemorySize, ATT_SMEM_BYTES);

    // 0. pre-round inputs to tf32
    round_tf32_kernel<<<(BT * D_MODEL / 4 + 255) / 256, 256>>>(x, xr, BT * D_MODEL / 4);
    round_tf32_kernel<<<(D3 * D_MODEL / 4 + 255) / 256, 256>>>(W_in, winr, D3 * D_MODEL / 4);
    round_tf32_kernel<<<(D_MODEL * D_MODEL / 4 + 255) / 256, 256>>>(W_out, woutr,
                                                                    D_MODEL * D_MODEL / 4);

    // 1. QKV projection; epilogue rounds to tf32 and pre-scales q by 1/8
    {
        dim3 grid(D3 / 128, BT / 128);
        gemm_tf32_kernel<0><<<grid, 256, GEMM_SMEM_BYTES>>>(xr, winr, qkv, BT, D3, D_MODEL);
    }

    // 2. causal flash attention (cvt-free, cp.async K/V, ldmatrix K)
    {
        dim3 grid(SEQ / QT, BATCH * N_HEADS);
        attn_mma_kernel<<<grid, 256, ATT_SMEM_BYTES>>>(qkv, attn);
    }

    // 3. output projection -> d_out
    {
        dim3 grid(D_MODEL / 128, BT / 128);
        gemm_tf32_kernel<1><<<grid, 256, GEMM_SMEM_BYTES>>>(attn, woutr, out, BT, D_MODEL, D_MODEL);
    }
}

// round 11
// speedup vs baseline: 1.2193x; 1.1043x over previous
#include <cuda_runtime.h>
#include <math.h>

#define D_MODEL 1024
#define N_HEADS 16
#define DH      64
#define BATCH   2
#define SEQ     2048
#define BT      (BATCH * SEQ)      // 4096
#define D3      (3 * D_MODEL)      // 3072

// ---------------- scratch (device globals; no allocation allowed) ----------
__device__ float g_xr[(size_t)BT * D_MODEL];          // x pre-rounded to tf32
__device__ float g_winr[(size_t)D3 * D_MODEL];        // W_in pre-rounded
__device__ float g_woutr[(size_t)D_MODEL * D_MODEL];  // W_out pre-rounded
// qkv: q,k as [bh][t][d] (q pre-scaled by 1/8); v TRANSPOSED as [bh][d][t]
__device__ float g_qkv[(size_t)3 * BT * D_MODEL];
__device__ float g_attn[(size_t)BT * D_MODEL];        // [B,T,D] tf32-rounded

// ---------------- helpers ----------------------------------------------------
__device__ __forceinline__ unsigned f2tf32(float f) {
    unsigned r;
    asm("cvt.rna.tf32.f32 %0, %1;" : "=r"(r) : "f"(f));
    return r;
}

__device__ __forceinline__ void mma_tf32(
    float& c0, float& c1, float& c2, float& c3,
    unsigned a0, unsigned a1, unsigned a2, unsigned a3,
    unsigned b0, unsigned b1) {
    asm volatile(
        "mma.sync.aligned.m16n8k8.row.col.f32.tf32.tf32.f32 "
        "{%0,%1,%2,%3}, {%4,%5,%6,%7}, {%8,%9}, {%0,%1,%2,%3};"
        : "+f"(c0), "+f"(c1), "+f"(c2), "+f"(c3)
        : "r"(a0), "r"(a1), "r"(a2), "r"(a3), "r"(b0), "r"(b1));
}

__device__ __forceinline__ void ldsm_x4(
    unsigned& r0, unsigned& r1, unsigned& r2, unsigned& r3, unsigned addr) {
    asm volatile("ldmatrix.sync.aligned.m8n8.x4.shared.b16 {%0,%1,%2,%3}, [%4];"
                 : "=r"(r0), "=r"(r1), "=r"(r2), "=r"(r3) : "r"(addr));
}

__device__ __forceinline__ unsigned smem_u32_of(const void* p) {
    unsigned r;
    asm("{ .reg .u64 t; cvta.to.shared.u64 t, %1; cvt.u32.u64 %0, t; }"
        : "=r"(r) : "l"(p));
    return r;
}

// ---------------- tf32 pre-rounding kernel ------------------------------------
__global__ __launch_bounds__(256) void round_tf32_kernel(
    const float* __restrict__ in, float* __restrict__ out, int n4) {
    int i = blockIdx.x * 256 + threadIdx.x;
    if (i < n4) {
        float4 v = ((const float4*)in)[i];
        ((uint4*)out)[i] =
            make_uint4(f2tf32(v.x), f2tf32(v.y), f2tf32(v.z), f2tf32(v.w));
    }
}

// ---------------- TF32 GEMM: C[M,N] = A[M,K] @ W[N,K]^T ----------------------
// Inputs pre-rounded tf32. Mainloop = LDSM + HMMA only (R9/R10, best measured).
// MODE 0 epilogue: rounds to tf32; q pre-scaled by 1/8; v written TRANSPOSED.
#define KSTEP 32
#define SPAD  36
#define STAGE_FLOATS (2 * 128 * SPAD)
#define STAGE_BYTES  (STAGE_FLOATS * 4)
#define GEMM_SMEM_BYTES (2 * STAGE_BYTES)               // 73728

template <int MODE>
__global__ __launch_bounds__(256, 2) void gemm_tf32_kernel(
    const float* __restrict__ A, const float* __restrict__ W,
    float* __restrict__ C, int M, int N, int K) {
    extern __shared__ float smem[];
    const unsigned smem_u32 = smem_u32_of(smem);

    const int tid  = threadIdx.x;
    const int lane = tid & 31;
    const int wid  = tid >> 5;
    const int warp_m = wid & 3;
    const int warp_n = wid >> 2;
    const int bm = blockIdx.y * 128;
    const int bn = blockIdx.x * 128;
    const int lr = lane >> 2;
    const int lc = lane & 3;

    const int c_row = tid >> 3;
    const int c_col = (tid & 7) * 4;
    const float* Abase = A + (size_t)(bm + c_row) * K + c_col;
    const float* Wbase = W + (size_t)(bn + c_row) * K + c_col;

    const int ls  = lane >> 3;
    const int rin = lane & 7;
    const int fr  = ((ls & 1) << 3) + rin;
    const int fc  = (ls >> 1) * 4;
    const unsigned a_off0 = (unsigned)(((warp_m * 32 + fr) * SPAD + fc) * 4);
    const unsigned a_off1 = (unsigned)(((warp_m * 32 + 16 + fr) * SPAD + fc) * 4);
    unsigned b_off[4];
    #pragma unroll
    for (int jj = 0; jj < 4; jj++)
        b_off[jj] = (unsigned)((128 * SPAD + (warp_n * 64 + jj * 16 + fr) * SPAD + fc) * 4);

#define COPY_TILE(k0, s) {                                                     \
        unsigned base_ = smem_u32 + (unsigned)((s) * STAGE_BYTES);             \
        _Pragma("unroll")                                                      \
        for (int it = 0; it < 4; it++) {                                       \
            int row_ = c_row + 32 * it;                                        \
            unsigned da_ = base_ + (unsigned)((row_ * SPAD + c_col) * 4);      \
            const float* sa_ = Abase + (size_t)(32 * it) * K + (k0);           \
            asm volatile("cp.async.cg.shared.global [%0], [%1], 16;"           \
                         :: "r"(da_), "l"(sa_));                               \
            unsigned db_ = base_ +                                             \
                (unsigned)((128 * SPAD + row_ * SPAD + c_col) * 4);            \
            const float* sb_ = Wbase + (size_t)(32 * it) * K + (k0);           \
            asm volatile("cp.async.cg.shared.global [%0], [%1], 16;"           \
                         :: "r"(db_), "l"(sb_));                               \
        }                                                                      \
        asm volatile("cp.async.commit_group;"); }

    float acc[2][8][4];
    #pragma unroll
    for (int i = 0; i < 2; i++)
        #pragma unroll
        for (int j = 0; j < 8; j++)
            #pragma unroll
            for (int c = 0; c < 4; c++) acc[i][j][c] = 0.f;

    COPY_TILE(0, 0);

    const int nk = K / KSTEP;
    for (int i = 0; i < nk; i++) {
        asm volatile("cp.async.wait_group 0;");
        __syncthreads();
        if (i + 1 < nk) COPY_TILE((i + 1) * KSTEP, (i + 1) & 1);

        const unsigned sbase = smem_u32 + (unsigned)((i & 1) * STAGE_BYTES);
        #pragma unroll
        for (int kk = 0; kk < KSTEP; kk += 8) {
            unsigned a[2][4];
            ldsm_x4(a[0][0], a[0][1], a[0][2], a[0][3], sbase + a_off0 + kk * 4);
            ldsm_x4(a[1][0], a[1][1], a[1][2], a[1][3], sbase + a_off1 + kk * 4);
            #pragma unroll
            for (int jj = 0; jj < 4; jj++) {
                unsigned b0a, b0b, b1a, b1b;
                ldsm_x4(b0a, b0b, b1a, b1b, sbase + b_off[jj] + kk * 4);
                int j0 = 2 * jj, j1 = 2 * jj + 1;
                mma_tf32(acc[0][j0][0], acc[0][j0][1], acc[0][j0][2], acc[0][j0][3],
                         a[0][0], a[0][1], a[0][2], a[0][3], b0a, b1a);
                mma_tf32(acc[1][j0][0], acc[1][j0][1], acc[1][j0][2], acc[1][j0][3],
                         a[1][0], a[1][1], a[1][2], a[1][3], b0a, b1a);
                mma_tf32(acc[0][j1][0], acc[0][j1][1], acc[0][j1][2], acc[0][j1][3],
                         a[0][0], a[0][1], a[0][2], a[0][3], b0b, b1b);
                mma_tf32(acc[1][j1][0], acc[1][j1][1], acc[1][j1][2], acc[1][j1][3],
                         a[1][0], a[1][1], a[1][2], a[1][3], b0b, b1b);
            }
        }
    }
#undef COPY_TILE

    #pragma unroll
    for (int i = 0; i < 2; i++) {
        #pragma unroll
        for (int j = 0; j < 8; j++) {
            #pragma unroll
            for (int c = 0; c < 4; c++) {
                int m = bm + warp_m * 32 + i * 16 + lr + ((c >= 2) ? 8 : 0);
                int n = bn + warp_n * 64 + j * 8 + 2 * lc + (c & 1);
                if (MODE == 0) {
                    int b = m >> 11;
                    int t = m & (SEQ - 1);
                    int which = n >> 10;
                    int d = n & (D_MODEL - 1);
                    int h = d >> 6;
                    int hd = d & 63;
                    float v = acc[i][j][c];
                    size_t dst;
                    if (which == 2) {
                        // V transposed: [bh][d][t]
                        dst = (size_t)2 * BT * D_MODEL +
                              (((size_t)(b * N_HEADS + h) * DH + hd) << 11) + t;
                    } else {
                        if (which == 0) v *= 0.125f;   // q pre-scaled
                        dst = (size_t)which * ((size_t)BT * D_MODEL) +
                              (((size_t)(b * N_HEADS + h) * SEQ + t) << 6) + hd;
                    }
                    C[dst] = __uint_as_float(f2tf32(v));
                } else {
                    C[(size_t)m * N + n] = acc[i][j][c];
                }
            }
        }
    }
}

// ---------------- TF32 tensor-core causal flash attention --------------------
// qkv tf32 bits (q pre-scaled, v transposed). cp.async double-buffered K/V^T,
// ldmatrix for K (B-op) AND V^T (A-op of O^T = V^T @ P^T). Cvt-free mainloop.
#define QT 128
#define KT 64
#define KS_PAD 68
#define ATT_STAGE_FLOATS (2 * KT * KS_PAD)             // K + V^T regions, 8704
#define ATT_STAGE_BYTES  (ATT_STAGE_FLOATS * 4)        // 34816
#define ATT_SMEM_BYTES   (2 * ATT_STAGE_BYTES)          // 69632
#define VT_REGION_BYTES  (KT * KS_PAD * 4)             // 17408

__global__ __launch_bounds__(256) void attn_mma_kernel(
    const float* __restrict__ qkv, float* __restrict__ out) {
    extern __shared__ float asmem[];
    const unsigned sm0 = smem_u32_of(asmem);

    const int tid  = threadIdx.x;
    const int lane = tid & 31;
    const int wid  = tid >> 5;
    const int lr = lane >> 2;
    const int lc = lane & 3;

    const int bh = blockIdx.y;
    const int qt = (gridDim.x - 1) - blockIdx.x;   // heavy tiles first
    const int q0 = qt * QT;

    const float* Qp  = qkv + ((size_t)bh * SEQ + q0) * DH;
    const float* Kp  = qkv + (size_t)BT * D_MODEL + (size_t)bh * SEQ * DH;
    const float* VTp = qkv + (size_t)2 * BT * D_MODEL + (size_t)bh * DH * SEQ;

    // ldmatrix lane offsets (R6-validated geometry)
    const int ls  = lane >> 3;
    const int rin = lane & 7;
    const int fr  = ((ls & 1) << 3) + rin;
    const int fc  = (ls >> 1) * 4;
    unsigned k_off[4];                               // K as B-operand (n=kv)
    #pragma unroll
    for (int jj = 0; jj < 4; jj++)
        k_off[jj] = (unsigned)(((jj * 16 + fr) * KS_PAD + fc) * 4);
    unsigned vt_off[4];                              // V^T as A-operand (m=d)
    #pragma unroll
    for (int mm = 0; mm < 4; mm++)
        vt_off[mm] = (unsigned)(VT_REGION_BYTES + ((mm * 16 + fr) * KS_PAD + fc) * 4);

#define ATT_COPY(k0, s) {                                                      \
        unsigned base_ = sm0 + (unsigned)((s) * ATT_STAGE_BYTES);              \
        _Pragma("unroll")                                                      \
        for (int it = 0; it < 4; it++) {                                       \
            int i_ = tid + 256 * it;                                           \
            int r_ = i_ >> 4;                                                  \
            int c_ = (i_ & 15) * 4;                                            \
            unsigned kd_ = base_ + (unsigned)((r_ * KS_PAD + c_) * 4);         \
            asm volatile("cp.async.cg.shared.global [%0], [%1], 16;"           \
                :: "r"(kd_), "l"(Kp + (size_t)((k0) + r_) * DH + c_));         \
            unsigned vd_ = base_ + (unsigned)(VT_REGION_BYTES +                \
                                              (r_ * KS_PAD + c_) * 4);         \
            asm volatile("cp.async.cg.shared.global [%0], [%1], 16;"           \
                :: "r"(vd_), "l"(VTp + (size_t)r_ * SEQ + (k0) + c_));         \
        }                                                                      \
        asm volatile("cp.async.commit_group;"); }

    // Q fragments: raw bit loads (already tf32, already scaled by 1/8)
    unsigned qa[8][4];
    {
        const int r0 = wid * 16 + lr;
        #pragma unroll
        for (int kk = 0; kk < 8; kk++) {
            int c = kk * 8 + lc;
            qa[kk][0] = __float_as_uint(Qp[(size_t)r0 * DH + c]);
            qa[kk][1] = __float_as_uint(Qp[(size_t)(r0 + 8) * DH + c]);
            qa[kk][2] = __float_as_uint(Qp[(size_t)r0 * DH + c + 4]);
            qa[kk][3] = __float_as_uint(Qp[(size_t)(r0 + 8) * DH + c + 4]);
        }
    }

    // O^T accumulator: [m-tile d][q-block][4]; lane holds (d=m*16+lr(+8), q=2lc(+1))
    float o[4][2][4];
    #pragma unroll
    for (int m = 0; m < 4; m++)
        #pragma unroll
        for (int jb = 0; jb < 2; jb++)
            #pragma unroll
            for (int c = 0; c < 4; c++) o[m][jb][c] = 0.f;
    float m0 = -1e30f, m1 = -1e30f, l0 = 0.f, l1 = 0.f;

    const int nkt = 2 * qt + 2;
    const int row0 = q0 + wid * 16 + lr;
    const int row1 = row0 + 8;

    ATT_COPY(0, 0);

    for (int kt = 0; kt < nkt; kt++) {
        const int k0 = kt * KT;
        const int s = kt & 1;
        asm volatile("cp.async.wait_group 0;");
        __syncthreads();
        if (kt + 1 < nkt) ATT_COPY((kt + 1) * KT, s ^ 1);

        const unsigned ksbase = sm0 + (unsigned)(s * ATT_STAGE_BYTES);

        // ---- S = (Q/8) @ K^T via ldmatrix ----
        float sv[8][4];
        #pragma unroll
        for (int n = 0; n < 8; n++)
            #pragma unroll
            for (int c = 0; c < 4; c++) sv[n][c] = 0.f;

        #pragma unroll
        for (int kk = 0; kk < 8; kk++) {
            #pragma unroll
            for (int jj = 0; jj < 4; jj++) {
                unsigned b0a, b0b, b1a, b1b;
                ldsm_x4(b0a, b0b, b1a, b1b, ksbase + k_off[jj] + kk * 32);
                int n0 = 2 * jj, n1 = 2 * jj + 1;
                mma_tf32(sv[n0][0], sv[n0][1], sv[n0][2], sv[n0][3],
                         qa[kk][0], qa[kk][1], qa[kk][2], qa[kk][3], b0a, b1a);
                mma_tf32(sv[n1][0], sv[n1][1], sv[n1][2], sv[n1][3],
                         qa[kk][0], qa[kk][1], qa[kk][2], qa[kk][3], b0b, b1b);
            }
        }

        if (kt >= 2 * qt) {
            #pragma unroll
            for (int n = 0; n < 8; n++) {
                int col0 = k0 + n * 8 + 2 * lc;
                if (col0 > row0)     sv[n][0] = -1e30f;
                if (col0 + 1 > row0) sv[n][1] = -1e30f;
                if (col0 > row1)     sv[n][2] = -1e30f;
                if (col0 + 1 > row1) sv[n][3] = -1e30f;
            }
        }

        float mx0 = -1e30f, mx1 = -1e30f;
        #pragma unroll
        for (int n = 0; n < 8; n++) {
            mx0 = fmaxf(mx0, fmaxf(sv[n][0], sv[n][1]));
            mx1 = fmaxf(mx1, fmaxf(sv[n][2], sv[n][3]));
        }
        mx0 = fmaxf(mx0, __shfl_xor_sync(0xffffffffu, mx0, 1));
        mx0 = fmaxf(mx0, __shfl_xor_sync(0xffffffffu, mx0, 2));
        mx1 = fmaxf(mx1, __shfl_xor_sync(0xffffffffu, mx1, 1));
        mx1 = fmaxf(mx1, __shfl_xor_sync(0xffffffffu, mx1, 2));

        float mn0 = fmaxf(m0, mx0), mn1 = fmaxf(m1, mx1);
        float alpha0 = __expf(m0 - mn0), alpha1 = __expf(m1 - mn1);
        m0 = mn0; m1 = mn1;

        float sum0 = 0.f, sum1 = 0.f;
        #pragma unroll
        for (int n = 0; n < 8; n++) {
            sv[n][0] = __expf(sv[n][0] - mn0);
            sv[n][1] = __expf(sv[n][1] - mn0);
            sv[n][2] = __expf(sv[n][2] - mn1);
            sv[n][3] = __expf(sv[n][3] - mn1);
            sum0 += sv[n][0] + sv[n][1];
            sum1 += sv[n][2] + sv[n][3];
        }
        sum0 += __shfl_xor_sync(0xffffffffu, sum0, 1);
        sum0 += __shfl_xor_sync(0xffffffffu, sum0, 2);
        sum1 += __shfl_xor_sync(0xffffffffu, sum1, 1);
        sum1 += __shfl_xor_sync(0xffffffffu, sum1, 2);
        l0 = l0 * alpha0 + sum0;
        l1 = l1 * alpha1 + sum1;

        // rescale O^T: alpha indexed by this lane's q columns (2lc, 2lc+1)
        {
            float aA0 = __shfl_sync(0xffffffffu, alpha0, lc << 3);
            float aA1 = __shfl_sync(0xffffffffu, alpha0, (lc << 3) + 4);
            float aB0 = __shfl_sync(0xffffffffu, alpha1, lc << 3);
            float aB1 = __shfl_sync(0xffffffffu, alpha1, (lc << 3) + 4);
            #pragma unroll
            for (int m = 0; m < 4; m++) {
                o[m][0][0] *= aA0; o[m][0][1] *= aA1;
                o[m][0][2] *= aA0; o[m][0][3] *= aA1;
                o[m][1][0] *= aB0; o[m][1][1] *= aB1;
                o[m][1][2] *= aB0; o[m][1][3] *= aB1;
            }
        }

        // quad-shuffle transpose P: after this, {sv[kk][0],sv[kk][2]} is the
        // B fragment for q-block 0 and {sv[kk][1],sv[kk][3]} for q-block 1.
        const int qbase = lane & ~3;
        const int h0 = qbase + (lc >> 1);
        const int h1 = h0 + 2;
        const bool odd = lc & 1;
        #pragma unroll
        for (int n = 0; n < 8; n++) {
            float t0 = __shfl_sync(0xffffffffu, sv[n][0], h0);
            float t1 = __shfl_sync(0xffffffffu, sv[n][1], h0);
            float u0 = __shfl_sync(0xffffffffu, sv[n][0], h1);
            float u1 = __shfl_sync(0xffffffffu, sv[n][1], h1);
            float v0 = __shfl_sync(0xffffffffu, sv[n][2], h0);
            float v1 = __shfl_sync(0xffffffffu, sv[n][3], h0);
            float w0 = __shfl_sync(0xffffffffu, sv[n][2], h1);
            float w1 = __shfl_sync(0xffffffffu, sv[n][3], h1);
            sv[n][0] = __uint_as_float(f2tf32(odd ? t1 : t0));
            sv[n][1] = __uint_as_float(f2tf32(odd ? v1 : v0));
            sv[n][2] = __uint_as_float(f2tf32(odd ? u1 : u0));
            sv[n][3] = __uint_as_float(f2tf32(odd ? w1 : w0));
        }

        // ---- O^T += V^T @ P^T : A = V^T via ldmatrix, B = transposed P regs
        #pragma unroll
        for (int m = 0; m < 4; m++) {
            #pragma unroll
            for (int kk = 0; kk < 8; kk++) {
                unsigned a0, a1, a2, a3;
                ldsm_x4(a0, a1, a2, a3, ksbase + vt_off[m] + kk * 32);
                mma_tf32(o[m][0][0], o[m][0][1], o[m][0][2], o[m][0][3],
                         a0, a1, a2, a3,
                         __float_as_uint(sv[kk][0]), __float_as_uint(sv[kk][2]));
                mma_tf32(o[m][1][0], o[m][1][1], o[m][1][2], o[m][1][3],
                         a0, a1, a2, a3,
                         __float_as_uint(sv[kk][1]), __float_as_uint(sv[kk][3]));
            }
        }
    }
#undef ATT_COPY

    // ---- epilogue: O^T -> g_attn [B,T,D], tf32-rounded ----
    const int b = bh >> 4;
    const int h = bh & 15;
    const float i0 = 1.f / l0;
    const float i1 = 1.f / l1;
    const float iA0 = __shfl_sync(0xffffffffu, i0, lc << 3);
    const float iA1 = __shfl_sync(0xffffffffu, i0, (lc << 3) + 4);
    const float iB0 = __shfl_sync(0xffffffffu, i1, lc << 3);
    const float iB1 = __shfl_sync(0xffffffffu, i1, (lc << 3) + 4);
    #pragma unroll
    for (int m = 0; m < 4; m++) {
        #pragma unroll
        for (int jb = 0; jb < 2; jb++) {
            #pragma unroll
            for (int c = 0; c < 4; c++) {
                int d = m * 16 + lr + ((c >= 2) ? 8 : 0);
                int q = q0 + wid * 16 + jb * 8 + 2 * lc + (c & 1);
                float inv = jb ? ((c & 1) ? iB1 : iB0) : ((c & 1) ? iA1 : iA0);
                out[((size_t)(b * SEQ + q)) * D_MODEL + h * DH + d] =
                    __uint_as_float(f2tf32(o[m][jb][c] * inv));
            }
        }
    }
}

// ---------------- launch ------------------------------------------------------
extern "C" void kernel_launch(void* const* d_in, const int* in_sizes, int n_in,
                              void* d_out, int out_size) {
    const float* x     = (const float*)d_in[0];
    const float* W_in  = (const float*)d_in[1];
    const float* W_out = (const float*)d_in[2];
    float* out = (float*)d_out;

    float *xr, *winr, *woutr, *qkv, *attn;
    cudaGetSymbolAddress((void**)&xr,    g_xr);
    cudaGetSymbolAddress((void**)&winr,  g_winr);
    cudaGetSymbolAddress((void**)&woutr, g_woutr);
    cudaGetSymbolAddress((void**)&qkv,   g_qkv);
    cudaGetSymbolAddress((void**)&attn,  g_attn);

    cudaFuncSetAttribute(gemm_tf32_kernel<0>,
                         cudaFuncAttributeMaxDynamicSharedMemorySize, GEMM_SMEM_BYTES);
    cudaFuncSetAttribute(gemm_tf32_kernel<1>,
                         cudaFuncAttributeMaxDynamicSharedMemorySize, GEMM_SMEM_BYTES);
    cudaFuncSetAttribute(attn_mma_kernel,
                         cudaFuncAttributeMaxDynamicSharedMemorySize, ATT_SMEM_BYTES);

    // 0. pre-round inputs to tf32
    round_tf32_kernel<<<(BT * D_MODEL / 4 + 255) / 256, 256>>>(x, xr, BT * D_MODEL / 4);
    round_tf32_kernel<<<(D3 * D_MODEL / 4 + 255) / 256, 256>>>(W_in, winr, D3 * D_MODEL / 4);
    round_tf32_kernel<<<(D_MODEL * D_MODEL / 4 + 255) / 256, 256>>>(W_out, woutr,
                                                                    D_MODEL * D_MODEL / 4);

    // 1. QKV projection; epilogue rounds, pre-scales q, transposes v
    {
        dim3 grid(D3 / 128, BT / 128);
        gemm_tf32_kernel<0><<<grid, 256, GEMM_SMEM_BYTES>>>(xr, winr, qkv, BT, D3, D_MODEL);
    }

    // 2. causal flash attention (cvt-free, cp.async, ldmatrix K AND V^T)
    {
        dim3 grid(SEQ / QT, BATCH * N_HEADS);
        attn_mma_kernel<<<grid, 256, ATT_SMEM_BYTES>>>(qkv, attn);
    }

    // 3. output projection -> d_out
    {
        dim3 grid(D_MODEL / 128, BT / 128);
        gemm_tf32_kernel<1><<<grid, 256, GEMM_SMEM_BYTES>>>(attn, woutr, out, BT, D_MODEL, D_MODEL);
    }
}

// round 12
// speedup vs baseline: 2.0804x; 1.7063x over previous
#include <cuda_runtime.h>
#include <cuda_fp16.h>
#include <math.h>

#define D_MODEL 1024
#define N_HEADS 16
#define DH      64
#define BATCH   2
#define SEQ     2048
#define BT      (BATCH * SEQ)      // 4096
#define D3      (3 * D_MODEL)      // 3072

// ---------------- scratch (device globals; no allocation allowed) ----------
__device__ __half g_xh[(size_t)BT * D_MODEL];          // x in fp16
__device__ __half g_winh[(size_t)D3 * D_MODEL];        // W_in fp16
__device__ __half g_wouth[(size_t)D_MODEL * D_MODEL];  // W_out fp16
__device__ __half g_qkvh[(size_t)3 * BT * D_MODEL];    // [3][B*H][T][DH] fp16 (q pre-scaled)
__device__ __half g_attnh[(size_t)BT * D_MODEL];       // [B,T,D] fp16

// ---------------- helpers ----------------------------------------------------
__device__ __forceinline__ unsigned pack_f16x2(float lo, float hi) {
    unsigned r;
    asm("cvt.rn.f16x2.f32 %0, %1, %2;" : "=r"(r) : "f"(hi), "f"(lo));
    return r;
}

__device__ __forceinline__ void mma_f16(
    float& c0, float& c1, float& c2, float& c3,
    unsigned a0, unsigned a1, unsigned a2, unsigned a3,
    unsigned b0, unsigned b1) {
    asm volatile(
        "mma.sync.aligned.m16n8k16.row.col.f32.f16.f16.f32 "
        "{%0,%1,%2,%3}, {%4,%5,%6,%7}, {%8,%9}, {%0,%1,%2,%3};"
        : "+f"(c0), "+f"(c1), "+f"(c2), "+f"(c3)
        : "r"(a0), "r"(a1), "r"(a2), "r"(a3), "r"(b0), "r"(b1));
}

__device__ __forceinline__ void ldsm_x4(
    unsigned& r0, unsigned& r1, unsigned& r2, unsigned& r3, unsigned addr) {
    asm volatile("ldmatrix.sync.aligned.m8n8.x4.shared.b16 {%0,%1,%2,%3}, [%4];"
                 : "=r"(r0), "=r"(r1), "=r"(r2), "=r"(r3) : "r"(addr));
}
__device__ __forceinline__ void ldsm_x4_t(
    unsigned& r0, unsigned& r1, unsigned& r2, unsigned& r3, unsigned addr) {
    asm volatile("ldmatrix.sync.aligned.m8n8.x4.trans.shared.b16 {%0,%1,%2,%3}, [%4];"
                 : "=r"(r0), "=r"(r1), "=r"(r2), "=r"(r3) : "r"(addr));
}

__device__ __forceinline__ unsigned smem_u32_of(const void* p) {
    unsigned r;
    asm("{ .reg .u64 t; cvta.to.shared.u64 t, %1; cvt.u32.u64 %0, t; }"
        : "=r"(r) : "l"(p));
    return r;
}

// ---------------- fp32 -> fp16 prep kernel ------------------------------------
__global__ __launch_bounds__(256) void to_f16_kernel(
    const float* __restrict__ in, __half* __restrict__ out, int n4) {
    int i = blockIdx.x * 256 + threadIdx.x;
    if (i < n4) {
        float4 v = ((const float4*)in)[i];
        uint2 u;
        u.x = pack_f16x2(v.x, v.y);
        u.y = pack_f16x2(v.z, v.w);
        ((uint2*)out)[i] = u;
    }
}

// ---------------- FP16 GEMM: C[M,N] = A[M,K] @ W[N,K]^T ----------------------
// fp16 operands, fp32 accum. Block 128x128, k-step 64, cp.async 2-stage double
// buffer, ldmatrix fragments. Row pitch 72 halves (144B): r*144 mod 128 = r*16,
// conflict-free for every 8-row ldmatrix phase.
#define KSTEP 64
#define HPAD  72
#define OP_BYTES   (128 * HPAD * 2)                    // 18432 per operand
#define STAGE_BYTES (2 * OP_BYTES)                     // 36864
#define GEMM_SMEM_BYTES (2 * STAGE_BYTES)               // 73728

template <int MODE>
__global__ __launch_bounds__(256, 2) void gemm_f16_kernel(
    const __half* __restrict__ A, const __half* __restrict__ W,
    float* __restrict__ C, int M, int N, int K) {
    extern __shared__ char smem[];
    const unsigned smem_u32 = smem_u32_of(smem);

    const int tid  = threadIdx.x;
    const int lane = tid & 31;
    const int wid  = tid >> 5;
    const int warp_m = wid & 3;
    const int warp_n = wid >> 2;
    const int bm = blockIdx.y * 128;
    const int bn = blockIdx.x * 128;
    const int lr = lane >> 2;
    const int lc = lane & 3;

    // copy mapping: per operand 128 rows x 8 chunks(16B); thread does 4 chunks
    const int c_row = tid >> 1;            // 0..127
    const int c_ch  = (tid & 1) * 4;       // chunk 0 or 4 (then +1..+3)
    const __half* Abase = A + (size_t)(bm + c_row) * K;
    const __half* Wbase = W + (size_t)(bn + c_row) * K;

    // ldmatrix lane address components
    // A x4: row = m0 + (l&15), colbyte = kk*32 + (l>>4)*16
    const int a_row = lane & 15;
    const int a_cb  = (lane >> 4) * 16;
    // B x4 (no-trans, [n][k]): row = n0 + (l>>4)*8 + (l&7), colbyte = kk*32 + ((l&8)?16:0)
    const int b_row = ((lane >> 4) << 3) + (lane & 7);
    const int b_cb  = (lane & 8) ? 16 : 0;

    const unsigned a_base0 = (unsigned)((warp_m * 32 + a_row) * 144 + a_cb);
    const unsigned a_base1 = (unsigned)((warp_m * 32 + 16 + a_row) * 144 + a_cb);
    unsigned b_base[4];
    #pragma unroll
    for (int jn = 0; jn < 4; jn++)
        b_base[jn] = (unsigned)(OP_BYTES + (warp_n * 64 + jn * 16 + b_row) * 144 + b_cb);

#define COPY_TILE(k0, s) {                                                     \
        unsigned base_ = smem_u32 + (unsigned)((s) * STAGE_BYTES);             \
        _Pragma("unroll")                                                      \
        for (int q = 0; q < 4; q++) {                                          \
            int ch_ = c_ch + q;                                                \
            unsigned da_ = base_ + (unsigned)(c_row * 144 + ch_ * 16);         \
            asm volatile("cp.async.cg.shared.global [%0], [%1], 16;"           \
                :: "r"(da_), "l"(Abase + (k0) + ch_ * 8));                     \
            unsigned db_ = base_ + (unsigned)(OP_BYTES + c_row * 144 + ch_ * 16);\
            asm volatile("cp.async.cg.shared.global [%0], [%1], 16;"           \
                :: "r"(db_), "l"(Wbase + (k0) + ch_ * 8));                     \
        }                                                                      \
        asm volatile("cp.async.commit_group;"); }

    float acc[2][8][4];
    #pragma unroll
    for (int i = 0; i < 2; i++)
        #pragma unroll
        for (int j = 0; j < 8; j++)
            #pragma unroll
            for (int c = 0; c < 4; c++) acc[i][j][c] = 0.f;

    COPY_TILE(0, 0);

    const int nk = K / KSTEP;
    for (int i = 0; i < nk; i++) {
        asm volatile("cp.async.wait_group 0;");
        __syncthreads();
        if (i + 1 < nk) COPY_TILE((i + 1) * KSTEP, (i + 1) & 1);

        const unsigned sbase = smem_u32 + (unsigned)((i & 1) * STAGE_BYTES);
        #pragma unroll
        for (int kk = 0; kk < 4; kk++) {        // 4 x k16
            unsigned a[2][4];
            ldsm_x4(a[0][0], a[0][1], a[0][2], a[0][3], sbase + a_base0 + kk * 32);
            ldsm_x4(a[1][0], a[1][1], a[1][2], a[1][3], sbase + a_base1 + kk * 32);
            #pragma unroll
            for (int jn = 0; jn < 4; jn++) {
                unsigned r0, r1, r2, r3;
                ldsm_x4(r0, r1, r2, r3, sbase + b_base[jn] + kk * 32);
                int j0 = 2 * jn, j1 = 2 * jn + 1;
                mma_f16(acc[0][j0][0], acc[0][j0][1], acc[0][j0][2], acc[0][j0][3],
                        a[0][0], a[0][1], a[0][2], a[0][3], r0, r1);
                mma_f16(acc[1][j0][0], acc[1][j0][1], acc[1][j0][2], acc[1][j0][3],
                        a[1][0], a[1][1], a[1][2], a[1][3], r0, r1);
                mma_f16(acc[0][j1][0], acc[0][j1][1], acc[0][j1][2], acc[0][j1][3],
                        a[0][0], a[0][1], a[0][2], a[0][3], r2, r3);
                mma_f16(acc[1][j1][0], acc[1][j1][1], acc[1][j1][2], acc[1][j1][3],
                        a[1][0], a[1][1], a[1][2], a[1][3], r2, r3);
            }
        }
    }
#undef COPY_TILE

    // epilogue. MODE 0: write fp16 qkv (q pre-scaled by 1/8), half2 stores.
    //           MODE 1: write fp32 row-major.
    #pragma unroll
    for (int i = 0; i < 2; i++) {
        #pragma unroll
        for (int j = 0; j < 8; j++) {
            #pragma unroll
            for (int half_row = 0; half_row < 2; half_row++) {
                int m = bm + warp_m * 32 + i * 16 + lr + half_row * 8;
                int n = bn + warp_n * 64 + j * 8 + 2 * lc;       // even
                float v0 = acc[i][j][half_row * 2 + 0];
                float v1 = acc[i][j][half_row * 2 + 1];
                if (MODE == 0) {
                    int b = m >> 11;
                    int t = m & (SEQ - 1);
                    int which = n >> 10;
                    int d = n & (D_MODEL - 1);
                    int h = d >> 6;
                    int hd = d & 63;
                    if (which == 0) { v0 *= 0.125f; v1 *= 0.125f; }
                    size_t dst = (size_t)which * ((size_t)BT * D_MODEL) +
                                 (((size_t)(b * N_HEADS + h) * SEQ + t) << 6) + hd;
                    *(unsigned*)((__half*)C + dst) = pack_f16x2(v0, v1);
                } else {
                    C[(size_t)m * N + n]     = v0;
                    C[(size_t)m * N + n + 1] = v1;
                }
            }
        }
    }
}

// ---------------- FP16 tensor-core causal flash attention --------------------
// Q/K/V fp16 (q pre-scaled 1/8, V natural [kv][d]). cp.async 2-stage K/V,
// ldmatrix everywhere. P fragments come straight from packed S registers.
#define QT 128
#define KT 64
#define ATT_OP_BYTES   (KT * HPAD * 2)                 // 9216
#define ATT_STAGE_BYTES (2 * ATT_OP_BYTES)             // 18432
#define ATT_SMEM_BYTES  (2 * ATT_STAGE_BYTES)           // 36864

__global__ __launch_bounds__(256) void attn_f16_kernel(
    const __half* __restrict__ qkv, __half* __restrict__ out) {
    extern __shared__ char asmem[];
    const unsigned sm0 = smem_u32_of(asmem);

    const int tid  = threadIdx.x;
    const int lane = tid & 31;
    const int wid  = tid >> 5;
    const int lr = lane >> 2;
    const int lc = lane & 3;

    const int bh = blockIdx.y;
    const int qt = (gridDim.x - 1) - blockIdx.x;   // heavy tiles first
    const int q0 = qt * QT;

    const __half* Qp = qkv + ((size_t)bh * SEQ + q0) * DH;
    const __half* Kp = qkv + (size_t)BT * D_MODEL + (size_t)bh * SEQ * DH;
    const __half* Vp = qkv + (size_t)2 * BT * D_MODEL + (size_t)bh * SEQ * DH;

    // ldmatrix lane components
    // K (B, no-trans, [kv][d]): row = kv0 + (l>>4)*8 + (l&7), colbyte = kk*32 + ((l&8)?16:0)
    const int kb_row = ((lane >> 4) << 3) + (lane & 7);
    const int kb_cb  = (lane & 8) ? 16 : 0;
    // V (B, trans, [kv][d]): row = kv0 + ((l&8)?8:0) + (l&7), colbyte = m*32 + (l>>4)*16
    const int vb_row = ((lane & 8) ? 8 : 0) + (lane & 7);
    const int vb_cb  = (lane >> 4) * 16;

#define ATT_COPY(k0, s) {                                                      \
        unsigned base_ = sm0 + (unsigned)((s) * ATT_STAGE_BYTES);              \
        _Pragma("unroll")                                                      \
        for (int it = 0; it < 2; it++) {                                       \
            int i_ = tid + 256 * it;                                           \
            int r_ = i_ >> 3;                                                  \
            int ch_ = i_ & 7;                                                  \
            unsigned kd_ = base_ + (unsigned)(r_ * 144 + ch_ * 16);            \
            asm volatile("cp.async.cg.shared.global [%0], [%1], 16;"           \
                :: "r"(kd_), "l"(Kp + (size_t)((k0) + r_) * DH + ch_ * 8));    \
            unsigned vd_ = base_ + (unsigned)(ATT_OP_BYTES + r_ * 144 + ch_ * 16);\
            asm volatile("cp.async.cg.shared.global [%0], [%1], 16;"           \
                :: "r"(vd_), "l"(Vp + (size_t)((k0) + r_) * DH + ch_ * 8));    \
        }                                                                      \
        asm volatile("cp.async.commit_group;"); }

    // Q fragments (fp16, pre-scaled): A-layout, 4 k16 groups
    unsigned qa[4][4];
    {
        const int r0 = wid * 16 + lr;
        #pragma unroll
        for (int kk = 0; kk < 4; kk++) {
            int c = kk * 16 + 2 * lc;
            qa[kk][0] = *(const unsigned*)&Qp[(size_t)r0 * DH + c];
            qa[kk][1] = *(const unsigned*)&Qp[(size_t)(r0 + 8) * DH + c];
            qa[kk][2] = *(const unsigned*)&Qp[(size_t)r0 * DH + c + 8];
            qa[kk][3] = *(const unsigned*)&Qp[(size_t)(r0 + 8) * DH + c + 8];
        }
    }

    float o[8][4];
    #pragma unroll
    for (int n = 0; n < 8; n++)
        #pragma unroll
        for (int c = 0; c < 4; c++) o[n][c] = 0.f;
    float m0 = -1e30f, m1 = -1e30f, l0 = 0.f, l1 = 0.f;

    const int nkt = 2 * qt + 2;
    const int row0 = q0 + wid * 16 + lr;
    const int row1 = row0 + 8;

    ATT_COPY(0, 0);

    for (int kt = 0; kt < nkt; kt++) {
        const int k0 = kt * KT;
        const int s = kt & 1;
        asm volatile("cp.async.wait_group 0;");
        __syncthreads();
        if (kt + 1 < nkt) ATT_COPY((kt + 1) * KT, s ^ 1);

        const unsigned ksbase = sm0 + (unsigned)(s * ATT_STAGE_BYTES);

        // ---- S = (Q/8) @ K^T ----
        float sv[8][4];
        #pragma unroll
        for (int n = 0; n < 8; n++)
            #pragma unroll
            for (int c = 0; c < 4; c++) sv[n][c] = 0.f;

        #pragma unroll
        for (int kk = 0; kk < 4; kk++) {
            #pragma unroll
            for (int jn = 0; jn < 4; jn++) {
                unsigned r0, r1, r2, r3;
                ldsm_x4(r0, r1, r2, r3,
                        ksbase + (unsigned)((jn * 16 + kb_row) * 144 + kk * 32 + kb_cb));
                int n0 = 2 * jn, n1 = 2 * jn + 1;
                mma_f16(sv[n0][0], sv[n0][1], sv[n0][2], sv[n0][3],
                        qa[kk][0], qa[kk][1], qa[kk][2], qa[kk][3], r0, r1);
                mma_f16(sv[n1][0], sv[n1][1], sv[n1][2], sv[n1][3],
                        qa[kk][0], qa[kk][1], qa[kk][2], qa[kk][3], r2, r3);
            }
        }

        if (kt >= 2 * qt) {
            #pragma unroll
            for (int n = 0; n < 8; n++) {
                int col0 = k0 + n * 8 + 2 * lc;
                if (col0 > row0)     sv[n][0] = -1e30f;
                if (col0 + 1 > row0) sv[n][1] = -1e30f;
                if (col0 > row1)     sv[n][2] = -1e30f;
                if (col0 + 1 > row1) sv[n][3] = -1e30f;
            }
        }

        // ---- online softmax ----
        float mx0 = -1e30f, mx1 = -1e30f;
        #pragma unroll
        for (int n = 0; n < 8; n++) {
            mx0 = fmaxf(mx0, fmaxf(sv[n][0], sv[n][1]));
            mx1 = fmaxf(mx1, fmaxf(sv[n][2], sv[n][3]));
        }
        mx0 = fmaxf(mx0, __shfl_xor_sync(0xffffffffu, mx0, 1));
        mx0 = fmaxf(mx0, __shfl_xor_sync(0xffffffffu, mx0, 2));
        mx1 = fmaxf(mx1, __shfl_xor_sync(0xffffffffu, mx1, 1));
        mx1 = fmaxf(mx1, __shfl_xor_sync(0xffffffffu, mx1, 2));

        float mn0 = fmaxf(m0, mx0), mn1 = fmaxf(m1, mx1);
        float alpha0 = __expf(m0 - mn0), alpha1 = __expf(m1 - mn1);
        m0 = mn0; m1 = mn1;

        float sum0 = 0.f, sum1 = 0.f;
        #pragma unroll
        for (int n = 0; n < 8; n++) {
            sv[n][0] = __expf(sv[n][0] - mn0);
            sv[n][1] = __expf(sv[n][1] - mn0);
            sv[n][2] = __expf(sv[n][2] - mn1);
            sv[n][3] = __expf(sv[n][3] - mn1);
            sum0 += sv[n][0] + sv[n][1];
            sum1 += sv[n][2] + sv[n][3];
        }
        sum0 += __shfl_xor_sync(0xffffffffu, sum0, 1);
        sum0 += __shfl_xor_sync(0xffffffffu, sum0, 2);
        sum1 += __shfl_xor_sync(0xffffffffu, sum1, 1);
        sum1 += __shfl_xor_sync(0xffffffffu, sum1, 2);
        l0 = l0 * alpha0 + sum0;
        l1 = l1 * alpha1 + sum1;

        #pragma unroll
        for (int n = 0; n < 8; n++) {
            o[n][0] *= alpha0; o[n][1] *= alpha0;
            o[n][2] *= alpha1; o[n][3] *= alpha1;
        }

        // ---- O += P @ V : P fragments = packed S registers (NO transpose) ----
        #pragma unroll
        for (int kk = 0; kk < 4; kk++) {       // kv16 groups
            unsigned p0 = pack_f16x2(sv[2 * kk][0],     sv[2 * kk][1]);
            unsigned p1 = pack_f16x2(sv[2 * kk][2],     sv[2 * kk][3]);
            unsigned p2 = pack_f16x2(sv[2 * kk + 1][0], sv[2 * kk + 1][1]);
            unsigned p3 = pack_f16x2(sv[2 * kk + 1][2], sv[2 * kk + 1][3]);
            #pragma unroll
            for (int dm = 0; dm < 4; dm++) {   // d16 groups
                unsigned r0, r1, r2, r3;
                ldsm_x4_t(r0, r1, r2, r3,
                          ksbase + (unsigned)(ATT_OP_BYTES +
                              (kk * 16 + vb_row) * 144 + dm * 32 + vb_cb));
                int n0 = 2 * dm, n1 = 2 * dm + 1;
                mma_f16(o[n0][0], o[n0][1], o[n0][2], o[n0][3],
                        p0, p1, p2, p3, r0, r1);
                mma_f16(o[n1][0], o[n1][1], o[n1][2], o[n1][3],
                        p0, p1, p2, p3, r2, r3);
            }
        }
    }
#undef ATT_COPY

    // ---- epilogue: normalize, write fp16 [B,T,D] ----
    const int b = bh >> 4;
    const int h = bh & 15;
    const float inv0 = 1.f / l0;
    const float inv1 = 1.f / l1;
    #pragma unroll
    for (int n = 0; n < 8; n++) {
        int d = h * DH + n * 8 + 2 * lc;
        *(unsigned*)&out[((size_t)(b * SEQ + row0)) * D_MODEL + d] =
            pack_f16x2(o[n][0] * inv0, o[n][1] * inv0);
        *(unsigned*)&out[((size_t)(b * SEQ + row1)) * D_MODEL + d] =
            pack_f16x2(o[n][2] * inv1, o[n][3] * inv1);
    }
}

// ---------------- launch ------------------------------------------------------
extern "C" void kernel_launch(void* const* d_in, const int* in_sizes, int n_in,
                              void* d_out, int out_size) {
    const float* x     = (const float*)d_in[0];
    const float* W_in  = (const float*)d_in[1];
    const float* W_out = (const float*)d_in[2];
    float* out = (float*)d_out;

    __half *xh, *winh, *wouth, *qkvh, *attnh;
    cudaGetSymbolAddress((void**)&xh,    g_xh);
    cudaGetSymbolAddress((void**)&winh,  g_winh);
    cudaGetSymbolAddress((void**)&wouth, g_wouth);
    cudaGetSymbolAddress((void**)&qkvh,  g_qkvh);
    cudaGetSymbolAddress((void**)&attnh, g_attnh);

    cudaFuncSetAttribute(gemm_f16_kernel<0>,
                         cudaFuncAttributeMaxDynamicSharedMemorySize, GEMM_SMEM_BYTES);
    cudaFuncSetAttribute(gemm_f16_kernel<1>,
                         cudaFuncAttributeMaxDynamicSharedMemorySize, GEMM_SMEM_BYTES);
    cudaFuncSetAttribute(attn_f16_kernel,
                         cudaFuncAttributeMaxDynamicSharedMemorySize, ATT_SMEM_BYTES);

    // 0. convert inputs to fp16
    to_f16_kernel<<<(BT * D_MODEL / 4 + 255) / 256, 256>>>(x, xh, BT * D_MODEL / 4);
    to_f16_kernel<<<(D3 * D_MODEL / 4 + 255) / 256, 256>>>(W_in, winh, D3 * D_MODEL / 4);
    to_f16_kernel<<<(D_MODEL * D_MODEL / 4 + 255) / 256, 256>>>(W_out, wouth,
                                                                D_MODEL * D_MODEL / 4);

    // 1. QKV projection (fp16 mma k16); epilogue writes fp16 qkv, q pre-scaled
    {
        dim3 grid(D3 / 128, BT / 128);        // (24, 32)
        gemm_f16_kernel<0><<<grid, 256, GEMM_SMEM_BYTES>>>(
            xh, winh, (float*)qkvh, BT, D3, D_MODEL);
    }

    // 2. causal flash attention (fp16 mma, ldmatrix everywhere, no P transpose)
    {
        dim3 grid(SEQ / QT, BATCH * N_HEADS); // (16, 32)
        attn_f16_kernel<<<grid, 256, ATT_SMEM_BYTES>>>(qkvh, attnh);
    }

    // 3. output projection (fp16 mma) -> fp32 d_out
    {
        dim3 grid(D_MODEL / 128, BT / 128);   // (8, 32)
        gemm_f16_kernel<1><<<grid, 256, GEMM_SMEM_BYTES>>>(
            attnh, wouth, out, BT, D_MODEL, D_MODEL);
    }
}